// round 7
// baseline (speedup 1.0000x reference)
#include <cuda_runtime.h>
#include <cuda_fp16.h>
#include <cstdint>

#define BATCH 8
#define SEQ   1024
#define DIM   512
#define HEADS 8
#define DHEAD 64
#define SCALE 0.125f

#define QKV_ELEMS (BATCH*HEADS*SEQ*DHEAD)

// fp16 staging buffers (device globals: allocation-free rule)
__device__ __half g_xh [8192*512];
__device__ __half g_wqh[512*512];
__device__ __half g_wkh[512*512];
__device__ __half g_wvh[512*512];
__device__ __half g_woh[512*512];
__device__ __half g_q[QKV_ELEMS];
__device__ __half g_k[QKV_ELEMS];
__device__ __half g_v[QKV_ELEMS];
__device__ __half g_o[QKV_ELEMS];

__device__ __forceinline__ uint32_t smem_u32(const void* p) {
    uint32_t a;
    asm("{ .reg .u64 t; cvta.to.shared.u64 t, %1; cvt.u32.u64 %0, t; }" : "=r"(a) : "l"(p));
    return a;
}
__device__ __forceinline__ uint32_t h2u(float lo, float hi) {
    uint32_t u;
    asm("cvt.rn.f16x2.f32 %0, %1, %2;" : "=r"(u) : "f"(hi), "f"(lo));
    return u;
}

__device__ __forceinline__ void mma16816(float c[4], const uint32_t a[4],
                                         uint32_t b0, uint32_t b1) {
    asm volatile(
        "mma.sync.aligned.m16n8k16.row.col.f32.f16.f16.f32 "
        "{%0,%1,%2,%3}, {%4,%5,%6,%7}, {%8,%9}, {%0,%1,%2,%3};\n"
        : "+f"(c[0]), "+f"(c[1]), "+f"(c[2]), "+f"(c[3])
        : "r"(a[0]), "r"(a[1]), "r"(a[2]), "r"(a[3]), "r"(b0), "r"(b1));
}

#define LDSM_X4(d0, d1, d2, d3, addr) \
    asm volatile("ldmatrix.sync.aligned.m8n8.x4.shared.b16 {%0,%1,%2,%3}, [%4];" \
                 : "=r"(d0), "=r"(d1), "=r"(d2), "=r"(d3) : "r"(addr))
#define LDSM_X4_T(d0, d1, d2, d3, addr) \
    asm volatile("ldmatrix.sync.aligned.m8n8.x4.trans.shared.b16 {%0,%1,%2,%3}, [%4];" \
                 : "=r"(d0), "=r"(d1), "=r"(d2), "=r"(d3) : "r"(addr))

#define CP16(dst, src) \
    asm volatile("cp.async.cg.shared.global [%0], [%1], 16;" :: "r"(dst), "l"(src))
#define CP_COMMIT() asm volatile("cp.async.commit_group;")
#define CP_WAIT1()  asm volatile("cp.async.wait_group 1;")

// ---------------------------------------------------------------------------
// Convert fp32 inputs -> fp16 staging. 1310720 float4s total.
// ---------------------------------------------------------------------------
__global__ __launch_bounds__(256) void conv_k(
    const float* __restrict__ x,  const float* __restrict__ wq,
    const float* __restrict__ wk, const float* __restrict__ wv,
    const float* __restrict__ wo)
{
    const uint32_t i = blockIdx.x * 256 + threadIdx.x;
    const float* src; __half* dst; uint32_t off;
    if (i < 1048576u)      { src = x;  dst = g_xh;  off = i; }
    else if (i < 1114112u) { src = wq; dst = g_wqh; off = i - 1048576u; }
    else if (i < 1179648u) { src = wk; dst = g_wkh; off = i - 1114112u; }
    else if (i < 1245184u) { src = wv; dst = g_wvh; off = i - 1179648u; }
    else                   { src = wo; dst = g_woh; off = i - 1245184u; }
    float4 v = ((const float4*)src)[off];
    ((uint2*)dst)[off] = make_uint2(h2u(v.x, v.y), h2u(v.z, v.w));
}

// ===========================================================================
// QKV: C = X @ W^T scattered to [b,h,n,d] (fp16). CTA 128m x 128n, 128 thr
// (4 warps 2m x 2n, warp tile 64x64), k-block 64, 3-stage cp.async.
// smem: A 3x16KB @0 ; B 3x16KB @49152. 96KB dynamic.
// ===========================================================================
__global__ __launch_bounds__(128) void qkv_tc()
{
    extern __shared__ char dsm[];
    const uint32_t sb = smem_u32(dsm);
    const int tid = threadIdx.x, lane = tid & 31, wid = tid >> 5;
    const int nblk = blockIdx.x, m0 = blockIdx.y * 128, z = blockIdx.z;
    const __half* Wh = (z == 0) ? g_wqh : (z == 1) ? g_wkh : g_wvh;
    __half* out = (z == 0) ? g_q : (z == 1) ? g_k : g_v;

    // fills: row = tid (A 128 rows, B 128 rows), 8 chunks each
    const __half* asrc = g_xh + (size_t)(m0 + tid) * DIM;
    const __half* bsrc = Wh + (size_t)(nblk * 128 + tid) * DIM;
    const uint32_t adst = sb + tid * 128;
    const uint32_t bdst = sb + 49152 + tid * 128;

    auto fill = [&](int kt) {
        const int buf = kt % 3;
        #pragma unroll
        for (int c = 0; c < 8; c++) {
            uint32_t sw = (uint32_t)((c ^ (tid & 7)) << 4);
            CP16(adst + buf * 16384 + sw, asrc + kt * 64 + c * 8);
            CP16(bdst + buf * 16384 + sw, bsrc + kt * 64 + c * 8);
        }
    };
    fill(0); CP_COMMIT();
    fill(1); CP_COMMIT();

    const int wm = wid >> 1, wn = wid & 1;
    const int g = lane >> 2, tg = lane & 3;
    const int ar0 = wm * 64 + (lane & 15);
    const int acs = lane >> 4;
    const int br0 = wn * 64 + ((lane >> 4) << 3) + (lane & 7);
    const int bcs = (lane >> 3) & 1;

    float acc[4][8][4] = {};

    for (int kt = 0; kt < 8; kt++) {
        CP_WAIT1();
        __syncthreads();
        const uint32_t abuf = sb + (kt % 3) * 16384;
        const uint32_t bbuf = sb + 49152 + (kt % 3) * 16384;
        #pragma unroll
        for (int ik = 0; ik < 4; ik++) {
            uint32_t a[4][4];
            #pragma unroll
            for (int im = 0; im < 4; im++) {
                int r = ar0 + im * 16;
                uint32_t ad = abuf + r * 128 + (uint32_t)(((2 * ik + acs) ^ (r & 7)) << 4);
                LDSM_X4(a[im][0], a[im][1], a[im][2], a[im][3], ad);
            }
            #pragma unroll
            for (int nt2 = 0; nt2 < 4; nt2++) {
                int r = br0 + nt2 * 16;
                uint32_t bd = bbuf + r * 128 + (uint32_t)(((2 * ik + bcs) ^ (r & 7)) << 4);
                uint32_t b0, b1, b2, b3;
                LDSM_X4(b0, b1, b2, b3, bd);
                #pragma unroll
                for (int im = 0; im < 4; im++) {
                    mma16816(acc[im][2 * nt2],     a[im], b0, b1);
                    mma16816(acc[im][2 * nt2 + 1], a[im], b2, b3);
                }
            }
        }
        if (kt < 6) fill(kt + 2);
        CP_COMMIT();
    }

    const int b = m0 >> 10, ns0 = m0 & 1023;
    const int head = nblk * 2 + wn;
    #pragma unroll
    for (int im = 0; im < 4; im++) {
        int mrow = wm * 64 + im * 16 + g;
        __half* base = out + ((size_t)(b * HEADS + head) * SEQ + ns0 + mrow) * DHEAD;
        #pragma unroll
        for (int nt = 0; nt < 8; nt++) {
            int d = nt * 8 + 2 * tg;
            *(uint32_t*)(base + d)             = h2u(acc[im][nt][0], acc[im][nt][1]);
            *(uint32_t*)(base + 8 * DHEAD + d) = h2u(acc[im][nt][2], acc[im][nt][3]);
        }
    }
}

// ===========================================================================
// Attention: CTA per (qt, h, b): 128 q-rows, 128 thr (4 warps x 32q).
// Q frags hoisted; K/V 3-stage cp.async; PV A-frags direct from S accums;
// V^T via ldmatrix.trans. smem: Q 16KB @0; K 3x8KB @16384; V 3x8KB @40960.
// ===========================================================================
__global__ __launch_bounds__(128) void attn_tc()
{
    extern __shared__ char dsm[];
    const uint32_t sb = smem_u32(dsm);
    const int tid = threadIdx.x, lane = tid & 31, wid = tid >> 5;
    const int qt = blockIdx.x, h = blockIdx.y, b = blockIdx.z;
    const __half* Qg = g_q + ((size_t)(b * HEADS + h) * SEQ + qt * 128) * DHEAD;
    const __half* Kg = g_k + ((size_t)(b * HEADS + h) * SEQ) * DHEAD;
    const __half* Vg = g_v + ((size_t)(b * HEADS + h) * SEQ) * DHEAD;

    // Q fill: 128 rows, 1 thr/row, 8 chunks
    #pragma unroll
    for (int c = 0; c < 8; c++)
        CP16(sb + tid * 128 + ((c ^ (tid & 7)) << 4), Qg + tid * 64 + c * 8);

    // KV fill: 64 rows, 2 thr/row, 4 chunks each per matrix
    const int kvrow = tid >> 1, kvcb = (tid & 1) * 4;
    auto fillKV = [&](int t) {
        const int buf = t % 3;
        #pragma unroll
        for (int c = 0; c < 4; c++) {
            int cc = kvcb + c;
            uint32_t sw = kvrow * 128 + ((cc ^ (kvrow & 7)) << 4);
            CP16(sb + 16384 + buf * 8192 + sw, Kg + (size_t)(t * 64 + kvrow) * 64 + cc * 8);
            CP16(sb + 40960 + buf * 8192 + sw, Vg + (size_t)(t * 64 + kvrow) * 64 + cc * 8);
        }
    };
    fillKV(0); CP_COMMIT();      // group0: Q + KV0
    fillKV(1); CP_COMMIT();      // group1: KV1
    CP_WAIT1();                  // group0 done
    __syncthreads();

    const int g = lane >> 2, tg = lane & 3;
    uint32_t qf[4][2][4];
    {
        int cs = lane >> 4;
        #pragma unroll
        for (int im = 0; im < 2; im++) {
            int r = wid * 32 + im * 16 + (lane & 15);
            #pragma unroll
            for (int ik = 0; ik < 4; ik++) {
                uint32_t ad = sb + r * 128 + (uint32_t)(((2 * ik + cs) ^ (r & 7)) << 4);
                LDSM_X4(qf[ik][im][0], qf[ik][im][1], qf[ik][im][2], qf[ik][im][3], ad);
            }
        }
    }

    const int br0 = ((lane >> 4) << 3) + (lane & 7);       // K: rows = j
    const int bcs = (lane >> 3) & 1;
    const int vr0 = ((lane >> 3) & 1) * 8 + (lane & 7);    // V trans: rows = j
    const int vcs = lane >> 4;

    float oc[2][8][4] = {};
    float rs[2][2] = {};

    for (int t = 0; t < 16; t++) {
        if (t) { CP_WAIT1(); __syncthreads(); }
        const uint32_t kb = sb + 16384 + (t % 3) * 8192;
        const uint32_t vb = sb + 40960 + (t % 3) * 8192;

        // S = Q K^T
        float sc[2][8][4] = {};
        #pragma unroll
        for (int ik = 0; ik < 4; ik++) {
            #pragma unroll
            for (int nt2 = 0; nt2 < 4; nt2++) {
                int r = nt2 * 16 + br0;
                uint32_t bd = kb + r * 128 + (uint32_t)(((2 * ik + bcs) ^ (r & 7)) << 4);
                uint32_t b0, b1, b2, b3;
                LDSM_X4(b0, b1, b2, b3, bd);
                #pragma unroll
                for (int im = 0; im < 2; im++) {
                    mma16816(sc[im][2 * nt2],     qf[ik][im], b0, b1);
                    mma16816(sc[im][2 * nt2 + 1], qf[ik][im], b2, b3);
                }
            }
        }

        // P = exp(clip(S*scale)), running row sums
        #pragma unroll
        for (int im = 0; im < 2; im++)
            #pragma unroll
            for (int in = 0; in < 8; in++) {
                #pragma unroll
                for (int r = 0; r < 4; r++)
                    sc[im][in][r] = __expf(fminf(fmaxf(sc[im][in][r] * SCALE, 1e-6f), 1.0f));
                rs[im][0] += sc[im][in][0] + sc[im][in][1];
                rs[im][1] += sc[im][in][2] + sc[im][in][3];
            }

        // O += P V : A frags = cvt(sc), B via ldmatrix.trans
        #pragma unroll
        for (int jk = 0; jk < 4; jk++) {
            uint32_t a[2][4];
            #pragma unroll
            for (int im = 0; im < 2; im++) {
                a[im][0] = h2u(sc[im][2 * jk][0],     sc[im][2 * jk][1]);
                a[im][1] = h2u(sc[im][2 * jk][2],     sc[im][2 * jk][3]);
                a[im][2] = h2u(sc[im][2 * jk + 1][0], sc[im][2 * jk + 1][1]);
                a[im][3] = h2u(sc[im][2 * jk + 1][2], sc[im][2 * jk + 1][3]);
            }
            #pragma unroll
            for (int dt2 = 0; dt2 < 4; dt2++) {
                int r = jk * 16 + vr0;
                uint32_t bd = vb + r * 128 + (uint32_t)(((2 * dt2 + vcs) ^ (r & 7)) << 4);
                uint32_t b0, b1, b2, b3;
                LDSM_X4_T(b0, b1, b2, b3, bd);
                #pragma unroll
                for (int im = 0; im < 2; im++) {
                    mma16816(oc[im][2 * dt2],     a[im], b0, b1);
                    mma16816(oc[im][2 * dt2 + 1], a[im], b2, b3);
                }
            }
        }
        if (t < 14) fillKV(t + 2);
        CP_COMMIT();
    }

    #pragma unroll
    for (int im = 0; im < 2; im++) {
        rs[im][0] += __shfl_xor_sync(0xffffffffu, rs[im][0], 1);
        rs[im][0] += __shfl_xor_sync(0xffffffffu, rs[im][0], 2);
        rs[im][1] += __shfl_xor_sync(0xffffffffu, rs[im][1], 1);
        rs[im][1] += __shfl_xor_sync(0xffffffffu, rs[im][1], 2);
        const float inv0 = 1.0f / rs[im][0], inv1 = 1.0f / rs[im][1];
        __half* ob = g_o + ((size_t)(b * HEADS + h) * SEQ
                            + qt * 128 + wid * 32 + im * 16 + g) * DHEAD;
        #pragma unroll
        for (int dt = 0; dt < 8; dt++) {
            int d = dt * 8 + 2 * tg;
            *(uint32_t*)(ob + d)             = h2u(oc[im][dt][0] * inv0, oc[im][dt][1] * inv0);
            *(uint32_t*)(ob + 8 * DHEAD + d) = h2u(oc[im][dt][2] * inv1, oc[im][dt][3] * inv1);
        }
    }
}

// ===========================================================================
// Out-proj: out = concat(g_o) @ Wo^T + bo (fp32). 128 thr, warp 64x64,
// 3-stage pipeline, A gathered from [b,h,n,d] (k-block == one head).
// ===========================================================================
__global__ __launch_bounds__(128) void proj_tc(
    const float* __restrict__ bo, float* __restrict__ outp)
{
    extern __shared__ char dsm[];
    const uint32_t sb = smem_u32(dsm);
    const int tid = threadIdx.x, lane = tid & 31, wid = tid >> 5;
    const int nblk = blockIdx.x, m0 = blockIdx.y * 128;
    const int b = m0 >> 10, ns0 = m0 & 1023;

    const __half* bsrc = g_woh + (size_t)(nblk * 128 + tid) * DIM;
    const uint32_t adst = sb + tid * 128;
    const uint32_t bdst = sb + 49152 + tid * 128;

    auto fill = [&](int kt) {
        const int buf = kt % 3;
        const __half* asrc = g_o + ((size_t)(b * HEADS + kt) * SEQ + ns0 + tid) * DHEAD;
        #pragma unroll
        for (int c = 0; c < 8; c++) {
            uint32_t sw = (uint32_t)((c ^ (tid & 7)) << 4);
            CP16(adst + buf * 16384 + sw, asrc + c * 8);
            CP16(bdst + buf * 16384 + sw, bsrc + kt * 64 + c * 8);
        }
    };
    fill(0); CP_COMMIT();
    fill(1); CP_COMMIT();

    const int wm = wid >> 1, wn = wid & 1;
    const int g = lane >> 2, tg = lane & 3;
    const int ar0 = wm * 64 + (lane & 15);
    const int acs = lane >> 4;
    const int br0 = wn * 64 + ((lane >> 4) << 3) + (lane & 7);
    const int bcs = (lane >> 3) & 1;

    float acc[4][8][4] = {};

    for (int kt = 0; kt < 8; kt++) {
        CP_WAIT1();
        __syncthreads();
        const uint32_t abuf = sb + (kt % 3) * 16384;
        const uint32_t bbuf = sb + 49152 + (kt % 3) * 16384;
        #pragma unroll
        for (int ik = 0; ik < 4; ik++) {
            uint32_t a[4][4];
            #pragma unroll
            for (int im = 0; im < 4; im++) {
                int r = ar0 + im * 16;
                uint32_t ad = abuf + r * 128 + (uint32_t)(((2 * ik + acs) ^ (r & 7)) << 4);
                LDSM_X4(a[im][0], a[im][1], a[im][2], a[im][3], ad);
            }
            #pragma unroll
            for (int nt2 = 0; nt2 < 4; nt2++) {
                int r = br0 + nt2 * 16;
                uint32_t bd = bbuf + r * 128 + (uint32_t)(((2 * ik + bcs) ^ (r & 7)) << 4);
                uint32_t b0, b1, b2, b3;
                LDSM_X4(b0, b1, b2, b3, bd);
                #pragma unroll
                for (int im = 0; im < 4; im++) {
                    mma16816(acc[im][2 * nt2],     a[im], b0, b1);
                    mma16816(acc[im][2 * nt2 + 1], a[im], b2, b3);
                }
            }
        }
        if (kt < 6) fill(kt + 2);
        CP_COMMIT();
    }

    #pragma unroll
    for (int im = 0; im < 4; im++) {
        int mrow = m0 + wm * 64 + im * 16 + g;
        #pragma unroll
        for (int nt = 0; nt < 8; nt++) {
            int n = nblk * 128 + wn * 64 + nt * 8 + 2 * tg;
            float2 bias = *(const float2*)(bo + n);
            float* op = outp + (size_t)mrow * DIM + n;
            *(float2*)op = make_float2(acc[im][nt][0] + bias.x, acc[im][nt][1] + bias.y);
            *(float2*)(op + 8 * DIM) = make_float2(acc[im][nt][2] + bias.x,
                                                   acc[im][nt][3] + bias.y);
        }
    }
}

// ---------------------------------------------------------------------------
extern "C" void kernel_launch(void* const* d_in, const int* in_sizes, int n_in,
                              void* d_out, int out_size)
{
    (void)in_sizes; (void)n_in; (void)out_size;
    const float* x  = (const float*)d_in[0];
    const float* wq = (const float*)d_in[1];
    const float* wk = (const float*)d_in[2];
    const float* wv = (const float*)d_in[3];
    const float* wo = (const float*)d_in[4];
    const float* bo = (const float*)d_in[5];
    float* out = (float*)d_out;

    cudaFuncSetAttribute(qkv_tc,  cudaFuncAttributeMaxDynamicSharedMemorySize, 98304);
    cudaFuncSetAttribute(attn_tc, cudaFuncAttributeMaxDynamicSharedMemorySize, 65536);
    cudaFuncSetAttribute(proj_tc, cudaFuncAttributeMaxDynamicSharedMemorySize, 98304);

    conv_k<<<5120, 256>>>(x, wq, wk, wv, wo);
    qkv_tc<<<dim3(4, 64, 3), 128, 98304>>>();
    attn_tc<<<dim3(SEQ / 128, HEADS, BATCH), 128, 65536>>>();
    proj_tc<<<dim3(4, 64), 128, 98304>>>(bo, out);
}

// round 8
// speedup vs baseline: 1.2539x; 1.2539x over previous
#include <cuda_runtime.h>
#include <cuda_fp16.h>
#include <cstdint>

#define BATCH 8
#define SEQ   1024
#define DIM   512
#define HEADS 8
#define DHEAD 64
#define SCALE 0.125f

#define QKV_ELEMS (BATCH*HEADS*SEQ*DHEAD)

// fp16 staging buffers (device globals: allocation-free rule)
__device__ __half g_xh [8192*512];
__device__ __half g_wqh[512*512];
__device__ __half g_wkh[512*512];
__device__ __half g_wvh[512*512];
__device__ __half g_woh[512*512];
__device__ __half g_q[QKV_ELEMS];
__device__ __half g_k[QKV_ELEMS];
__device__ __half g_v[QKV_ELEMS];
__device__ __half g_o[QKV_ELEMS];

__device__ __forceinline__ uint32_t smem_u32(const void* p) {
    uint32_t a;
    asm("{ .reg .u64 t; cvta.to.shared.u64 t, %1; cvt.u32.u64 %0, t; }" : "=r"(a) : "l"(p));
    return a;
}
__device__ __forceinline__ uint32_t h2u(float lo, float hi) {
    uint32_t u;
    asm("cvt.rn.f16x2.f32 %0, %1, %2;" : "=r"(u) : "f"(hi), "f"(lo));
    return u;
}

__device__ __forceinline__ void mma16816(float c[4], const uint32_t a[4],
                                         uint32_t b0, uint32_t b1) {
    asm volatile(
        "mma.sync.aligned.m16n8k16.row.col.f32.f16.f16.f32 "
        "{%0,%1,%2,%3}, {%4,%5,%6,%7}, {%8,%9}, {%0,%1,%2,%3};\n"
        : "+f"(c[0]), "+f"(c[1]), "+f"(c[2]), "+f"(c[3])
        : "r"(a[0]), "r"(a[1]), "r"(a[2]), "r"(a[3]), "r"(b0), "r"(b1));
}

#define LDSM_X4(d0, d1, d2, d3, addr) \
    asm volatile("ldmatrix.sync.aligned.m8n8.x4.shared.b16 {%0,%1,%2,%3}, [%4];" \
                 : "=r"(d0), "=r"(d1), "=r"(d2), "=r"(d3) : "r"(addr))
#define LDSM_X4_T(d0, d1, d2, d3, addr) \
    asm volatile("ldmatrix.sync.aligned.m8n8.x4.trans.shared.b16 {%0,%1,%2,%3}, [%4];" \
                 : "=r"(d0), "=r"(d1), "=r"(d2), "=r"(d3) : "r"(addr))

#define CP16(dst, src) \
    asm volatile("cp.async.cg.shared.global [%0], [%1], 16;" :: "r"(dst), "l"(src))
#define CP_COMMIT() asm volatile("cp.async.commit_group;")
#define CP_WAIT1()  asm volatile("cp.async.wait_group 1;")

// ---------------------------------------------------------------------------
// Convert fp32 inputs -> fp16 staging. 1310720 float4s total.
// ---------------------------------------------------------------------------
__global__ __launch_bounds__(256) void conv_k(
    const float* __restrict__ x,  const float* __restrict__ wq,
    const float* __restrict__ wk, const float* __restrict__ wv,
    const float* __restrict__ wo)
{
    const uint32_t i = blockIdx.x * 256 + threadIdx.x;
    const float* src; __half* dst; uint32_t off;
    if (i < 1048576u)      { src = x;  dst = g_xh;  off = i; }
    else if (i < 1114112u) { src = wq; dst = g_wqh; off = i - 1048576u; }
    else if (i < 1179648u) { src = wk; dst = g_wkh; off = i - 1114112u; }
    else if (i < 1245184u) { src = wv; dst = g_wvh; off = i - 1179648u; }
    else                   { src = wo; dst = g_woh; off = i - 1245184u; }
    float4 v = ((const float4*)src)[off];
    ((uint2*)dst)[off] = make_uint2(h2u(v.x, v.y), h2u(v.z, v.w));
}

// ===========================================================================
// QKV: C = X @ W^T scattered to [b,h,n,d] (fp16). CTA 128m x 128n, 256 thr
// (8 warps 4m x 2n, warp 32x64), k-block 64, 3-stage cp.async, fragment
// double-buffering (prefetch ik+1 LDSMs during ik MMAs).
// smem: A 3x16KB @0 ; B 3x16KB @49152. 96KB dynamic.
// ===========================================================================
__global__ __launch_bounds__(256, 2) void qkv_tc()
{
    extern __shared__ char dsm[];
    const uint32_t sb = smem_u32(dsm);
    const int tid = threadIdx.x, lane = tid & 31, wid = tid >> 5;
    const int nblk = blockIdx.x, m0 = blockIdx.y * 128, z = blockIdx.z;
    const __half* Wh = (z == 0) ? g_wqh : (z == 1) ? g_wkh : g_wvh;
    __half* out = (z == 0) ? g_q : (z == 1) ? g_k : g_v;

    const int arow = tid >> 1, cb = (tid & 1) * 4;
    const __half* asrc = g_xh + (size_t)(m0 + arow) * DIM + cb * 8;
    const __half* bsrc = Wh + (size_t)(nblk * 128 + arow) * DIM + cb * 8;
    const uint32_t adst = sb + arow * 128;
    const uint32_t bdst = sb + 49152 + arow * 128;

    auto fill = [&](int kt) {
        const int buf = kt % 3;
        #pragma unroll
        for (int c = 0; c < 4; c++) {
            int cc = cb + c;
            uint32_t sw = (uint32_t)((cc ^ (arow & 7)) << 4);
            CP16(adst + buf * 16384 + sw, asrc + kt * 64 + c * 8);
            CP16(bdst + buf * 16384 + sw, bsrc + kt * 64 + c * 8);
        }
    };
    fill(0); CP_COMMIT();
    fill(1); CP_COMMIT();

    const int wm = wid >> 1, wn = wid & 1;
    const int g = lane >> 2, tg = lane & 3;
    const int ar0 = wm * 32 + (lane & 15);
    const int acs = lane >> 4;
    const int br0 = wn * 64 + ((lane >> 4) << 3) + (lane & 7);
    const int bcs = (lane >> 3) & 1;

    auto ldA = [&](uint32_t abuf, int ik, uint32_t af[2][4]) {
        #pragma unroll
        for (int im = 0; im < 2; im++) {
            int r = ar0 + im * 16;
            uint32_t ad = abuf + r * 128 + (uint32_t)(((2 * ik + acs) ^ (r & 7)) << 4);
            LDSM_X4(af[im][0], af[im][1], af[im][2], af[im][3], ad);
        }
    };
    auto ldB = [&](uint32_t bbuf, int ik, uint32_t bf[4][4]) {
        #pragma unroll
        for (int nt2 = 0; nt2 < 4; nt2++) {
            int r = br0 + nt2 * 16;
            uint32_t bd = bbuf + r * 128 + (uint32_t)(((2 * ik + bcs) ^ (r & 7)) << 4);
            LDSM_X4(bf[nt2][0], bf[nt2][1], bf[nt2][2], bf[nt2][3], bd);
        }
    };

    float acc[2][8][4] = {};
    uint32_t afr[2][2][4], bfr[2][4][4];

    for (int kt = 0; kt < 8; kt++) {
        CP_WAIT1();
        __syncthreads();
        const uint32_t abuf = sb + (kt % 3) * 16384;
        const uint32_t bbuf = sb + 49152 + (kt % 3) * 16384;
        ldA(abuf, 0, afr[0]);
        ldB(bbuf, 0, bfr[0]);
        #pragma unroll
        for (int ik = 0; ik < 4; ik++) {
            const int cur = ik & 1;
            if (ik < 3) {
                ldA(abuf, ik + 1, afr[cur ^ 1]);
                ldB(bbuf, ik + 1, bfr[cur ^ 1]);
            }
            #pragma unroll
            for (int nt2 = 0; nt2 < 4; nt2++)
                #pragma unroll
                for (int im = 0; im < 2; im++) {
                    mma16816(acc[im][2 * nt2],     afr[cur][im], bfr[cur][nt2][0], bfr[cur][nt2][1]);
                    mma16816(acc[im][2 * nt2 + 1], afr[cur][im], bfr[cur][nt2][2], bfr[cur][nt2][3]);
                }
        }
        if (kt < 6) fill(kt + 2);
        CP_COMMIT();
    }

    const int b = m0 >> 10, ns0 = m0 & 1023;
    const int head = nblk * 2 + wn;
    #pragma unroll
    for (int im = 0; im < 2; im++) {
        int mrow = wm * 32 + im * 16 + g;
        __half* base = out + ((size_t)(b * HEADS + head) * SEQ + ns0 + mrow) * DHEAD;
        #pragma unroll
        for (int nt = 0; nt < 8; nt++) {
            int d = nt * 8 + 2 * tg;
            *(uint32_t*)(base + d)             = h2u(acc[im][nt][0], acc[im][nt][1]);
            *(uint32_t*)(base + 8 * DHEAD + d) = h2u(acc[im][nt][2], acc[im][nt][3]);
        }
    }
}

// ===========================================================================
// Attention: CTA per (qt, h, b): 128 q-rows, 256 thr (8 warps x 16q).
// Q frags hoisted; K/V 3-stage cp.async; fragment double-buffering in both
// S and PV loops; PV A-frags direct from S accums; V^T via ldmatrix.trans.
// smem: Q 16KB @0; K 3x8KB @16384; V 3x8KB @40960.
// ===========================================================================
__global__ __launch_bounds__(256, 2) void attn_tc()
{
    extern __shared__ char dsm[];
    const uint32_t sb = smem_u32(dsm);
    const int tid = threadIdx.x, lane = tid & 31, wid = tid >> 5;
    const int qt = blockIdx.x, h = blockIdx.y, b = blockIdx.z;
    const __half* Qg = g_q + ((size_t)(b * HEADS + h) * SEQ + qt * 128) * DHEAD;
    const __half* Kg = g_k + ((size_t)(b * HEADS + h) * SEQ) * DHEAD;
    const __half* Vg = g_v + ((size_t)(b * HEADS + h) * SEQ) * DHEAD;

    // Q fill: 128 rows, 2 thr/row, 4 chunks each
    {
        const int row = tid >> 1, cq = (tid & 1) * 4;
        #pragma unroll
        for (int c = 0; c < 4; c++) {
            int cc = cq + c;
            CP16(sb + row * 128 + ((cc ^ (row & 7)) << 4), Qg + row * 64 + cc * 8);
        }
    }
    // KV fill: 64 rows, 4 thr/row, 2 chunks each per matrix
    const int kvrow = tid >> 2, kvcb = (tid & 3) * 2;
    auto fillKV = [&](int t) {
        const int buf = t % 3;
        #pragma unroll
        for (int c = 0; c < 2; c++) {
            int cc = kvcb + c;
            uint32_t sw = kvrow * 128 + ((cc ^ (kvrow & 7)) << 4);
            CP16(sb + 16384 + buf * 8192 + sw, Kg + (size_t)(t * 64 + kvrow) * 64 + cc * 8);
            CP16(sb + 40960 + buf * 8192 + sw, Vg + (size_t)(t * 64 + kvrow) * 64 + cc * 8);
        }
    };
    fillKV(0); CP_COMMIT();      // group0: Q + KV0
    fillKV(1); CP_COMMIT();      // group1: KV1
    CP_WAIT1();                  // group0 done
    __syncthreads();

    const int g = lane >> 2, tg = lane & 3;
    uint32_t qf[4][4];
    {
        int r = wid * 16 + (lane & 15);
        int cs = lane >> 4;
        #pragma unroll
        for (int ik = 0; ik < 4; ik++) {
            uint32_t ad = sb + r * 128 + (uint32_t)(((2 * ik + cs) ^ (r & 7)) << 4);
            LDSM_X4(qf[ik][0], qf[ik][1], qf[ik][2], qf[ik][3], ad);
        }
    }

    const int br0 = ((lane >> 4) << 3) + (lane & 7);       // K: rows = j
    const int bcs = (lane >> 3) & 1;
    const int vr0 = ((lane >> 3) & 1) * 8 + (lane & 7);    // V trans: rows = j
    const int vcs = lane >> 4;

    auto ldK = [&](uint32_t kb, int ik, int nt2, uint32_t f[4]) {
        int r = nt2 * 16 + br0;
        uint32_t bd = kb + r * 128 + (uint32_t)(((2 * ik + bcs) ^ (r & 7)) << 4);
        LDSM_X4(f[0], f[1], f[2], f[3], bd);
    };
    auto ldV = [&](uint32_t vb, int jk, int dt2, uint32_t f[4]) {
        int r = jk * 16 + vr0;
        uint32_t bd = vb + r * 128 + (uint32_t)(((2 * dt2 + vcs) ^ (r & 7)) << 4);
        LDSM_X4_T(f[0], f[1], f[2], f[3], bd);
    };

    float oc[8][4] = {};
    float rsum0 = 0.f, rsum1 = 0.f;

    for (int t = 0; t < 16; t++) {
        if (t) { CP_WAIT1(); __syncthreads(); }
        const uint32_t kb = sb + 16384 + (t % 3) * 8192;
        const uint32_t vb = sb + 40960 + (t % 3) * 8192;

        // ---- S = Q K^T, pipelined over flattened (ik, nt2) ----
        float sc[8][4] = {};
        uint32_t kf[2][4];
        ldK(kb, 0, 0, kf[0]);
        #pragma unroll
        for (int s = 0; s < 16; s++) {
            const int ik = s >> 2, nt2 = s & 3, cur = s & 1;
            if (s < 15) ldK(kb, (s + 1) >> 2, (s + 1) & 3, kf[cur ^ 1]);
            mma16816(sc[2 * nt2],     qf[ik], kf[cur][0], kf[cur][1]);
            mma16816(sc[2 * nt2 + 1], qf[ik], kf[cur][2], kf[cur][3]);
        }

        // ---- P = exp(clip(S*scale)), running row sums ----
        #pragma unroll
        for (int in = 0; in < 8; in++) {
            #pragma unroll
            for (int r = 0; r < 4; r++)
                sc[in][r] = __expf(fminf(fmaxf(sc[in][r] * SCALE, 1e-6f), 1.0f));
            rsum0 += sc[in][0] + sc[in][1];
            rsum1 += sc[in][2] + sc[in][3];
        }

        // ---- O += P V, pipelined over flattened (jk, dt2) ----
        uint32_t vf[2][4];
        uint32_t a[4];
        ldV(vb, 0, 0, vf[0]);
        #pragma unroll
        for (int s = 0; s < 16; s++) {
            const int jk = s >> 2, dt2 = s & 3, cur = s & 1;
            if (dt2 == 0) {
                a[0] = h2u(sc[2 * jk][0],     sc[2 * jk][1]);
                a[1] = h2u(sc[2 * jk][2],     sc[2 * jk][3]);
                a[2] = h2u(sc[2 * jk + 1][0], sc[2 * jk + 1][1]);
                a[3] = h2u(sc[2 * jk + 1][2], sc[2 * jk + 1][3]);
            }
            if (s < 15) ldV(vb, (s + 1) >> 2, (s + 1) & 3, vf[cur ^ 1]);
            mma16816(oc[2 * dt2],     a, vf[cur][0], vf[cur][1]);
            mma16816(oc[2 * dt2 + 1], a, vf[cur][2], vf[cur][3]);
        }
        if (t < 14) fillKV(t + 2);
        CP_COMMIT();
    }

    rsum0 += __shfl_xor_sync(0xffffffffu, rsum0, 1);
    rsum0 += __shfl_xor_sync(0xffffffffu, rsum0, 2);
    rsum1 += __shfl_xor_sync(0xffffffffu, rsum1, 1);
    rsum1 += __shfl_xor_sync(0xffffffffu, rsum1, 2);
    const float inv0 = 1.0f / rsum0, inv1 = 1.0f / rsum1;

    __half* ob = g_o + ((size_t)(b * HEADS + h) * SEQ + qt * 128 + wid * 16 + g) * DHEAD;
    #pragma unroll
    for (int dt = 0; dt < 8; dt++) {
        int d = dt * 8 + 2 * tg;
        *(uint32_t*)(ob + d)             = h2u(oc[dt][0] * inv0, oc[dt][1] * inv0);
        *(uint32_t*)(ob + 8 * DHEAD + d) = h2u(oc[dt][2] * inv1, oc[dt][3] * inv1);
    }
}

// ===========================================================================
// Out-proj: out = concat(g_o) @ Wo^T + bo (fp32). Same structure as qkv_tc
// (fragment-pipelined); A gathered from [b,h,n,d] (k-block == one head).
// ===========================================================================
__global__ __launch_bounds__(256, 2) void proj_tc(
    const float* __restrict__ bo, float* __restrict__ outp)
{
    extern __shared__ char dsm[];
    const uint32_t sb = smem_u32(dsm);
    const int tid = threadIdx.x, lane = tid & 31, wid = tid >> 5;
    const int nblk = blockIdx.x, m0 = blockIdx.y * 128;
    const int b = m0 >> 10, ns0 = m0 & 1023;

    const int arow = tid >> 1, cb = (tid & 1) * 4;
    const __half* bsrc = g_woh + (size_t)(nblk * 128 + arow) * DIM + cb * 8;
    const uint32_t adst = sb + arow * 128;
    const uint32_t bdst = sb + 49152 + arow * 128;

    auto fill = [&](int kt) {
        const int buf = kt % 3;
        const __half* asrc = g_o + ((size_t)(b * HEADS + kt) * SEQ + ns0 + arow) * DHEAD + cb * 8;
        #pragma unroll
        for (int c = 0; c < 4; c++) {
            int cc = cb + c;
            uint32_t sw = (uint32_t)((cc ^ (arow & 7)) << 4);
            CP16(adst + buf * 16384 + sw, asrc + c * 8);
            CP16(bdst + buf * 16384 + sw, bsrc + kt * 64 + c * 8);
        }
    };
    fill(0); CP_COMMIT();
    fill(1); CP_COMMIT();

    const int wm = wid >> 1, wn = wid & 1;
    const int g = lane >> 2, tg = lane & 3;
    const int ar0 = wm * 32 + (lane & 15);
    const int acs = lane >> 4;
    const int br0 = wn * 64 + ((lane >> 4) << 3) + (lane & 7);
    const int bcs = (lane >> 3) & 1;

    auto ldA = [&](uint32_t abuf, int ik, uint32_t af[2][4]) {
        #pragma unroll
        for (int im = 0; im < 2; im++) {
            int r = ar0 + im * 16;
            uint32_t ad = abuf + r * 128 + (uint32_t)(((2 * ik + acs) ^ (r & 7)) << 4);
            LDSM_X4(af[im][0], af[im][1], af[im][2], af[im][3], ad);
        }
    };
    auto ldB = [&](uint32_t bbuf, int ik, uint32_t bf[4][4]) {
        #pragma unroll
        for (int nt2 = 0; nt2 < 4; nt2++) {
            int r = br0 + nt2 * 16;
            uint32_t bd = bbuf + r * 128 + (uint32_t)(((2 * ik + bcs) ^ (r & 7)) << 4);
            LDSM_X4(bf[nt2][0], bf[nt2][1], bf[nt2][2], bf[nt2][3], bd);
        }
    };

    float acc[2][8][4] = {};
    uint32_t afr[2][2][4], bfr[2][4][4];

    for (int kt = 0; kt < 8; kt++) {
        CP_WAIT1();
        __syncthreads();
        const uint32_t abuf = sb + (kt % 3) * 16384;
        const uint32_t bbuf = sb + 49152 + (kt % 3) * 16384;
        ldA(abuf, 0, afr[0]);
        ldB(bbuf, 0, bfr[0]);
        #pragma unroll
        for (int ik = 0; ik < 4; ik++) {
            const int cur = ik & 1;
            if (ik < 3) {
                ldA(abuf, ik + 1, afr[cur ^ 1]);
                ldB(bbuf, ik + 1, bfr[cur ^ 1]);
            }
            #pragma unroll
            for (int nt2 = 0; nt2 < 4; nt2++)
                #pragma unroll
                for (int im = 0; im < 2; im++) {
                    mma16816(acc[im][2 * nt2],     afr[cur][im], bfr[cur][nt2][0], bfr[cur][nt2][1]);
                    mma16816(acc[im][2 * nt2 + 1], afr[cur][im], bfr[cur][nt2][2], bfr[cur][nt2][3]);
                }
        }
        if (kt < 6) fill(kt + 2);
        CP_COMMIT();
    }

    #pragma unroll
    for (int im = 0; im < 2; im++) {
        int mrow = m0 + wm * 32 + im * 16 + g;
        #pragma unroll
        for (int nt = 0; nt < 8; nt++) {
            int n = nblk * 128 + wn * 64 + nt * 8 + 2 * tg;
            float2 bias = *(const float2*)(bo + n);
            float* op = outp + (size_t)mrow * DIM + n;
            *(float2*)op = make_float2(acc[im][nt][0] + bias.x, acc[im][nt][1] + bias.y);
            *(float2*)(op + 8 * DIM) = make_float2(acc[im][nt][2] + bias.x,
                                                   acc[im][nt][3] + bias.y);
        }
    }
}

// ---------------------------------------------------------------------------
extern "C" void kernel_launch(void* const* d_in, const int* in_sizes, int n_in,
                              void* d_out, int out_size)
{
    (void)in_sizes; (void)n_in; (void)out_size;
    const float* x  = (const float*)d_in[0];
    const float* wq = (const float*)d_in[1];
    const float* wk = (const float*)d_in[2];
    const float* wv = (const float*)d_in[3];
    const float* wo = (const float*)d_in[4];
    const float* bo = (const float*)d_in[5];
    float* out = (float*)d_out;

    cudaFuncSetAttribute(qkv_tc,  cudaFuncAttributeMaxDynamicSharedMemorySize, 98304);
    cudaFuncSetAttribute(attn_tc, cudaFuncAttributeMaxDynamicSharedMemorySize, 65536);
    cudaFuncSetAttribute(proj_tc, cudaFuncAttributeMaxDynamicSharedMemorySize, 98304);

    conv_k<<<5120, 256>>>(x, wq, wk, wv, wo);
    qkv_tc<<<dim3(4, 64, 3), 256, 98304>>>();
    attn_tc<<<dim3(SEQ / 128, HEADS, BATCH), 256, 65536>>>();
    proj_tc<<<dim3(4, 64), 256, 98304>>>(bo, out);
}

// round 9
// speedup vs baseline: 1.3117x; 1.0461x over previous
#include <cuda_runtime.h>
#include <cuda_fp16.h>
#include <cstdint>

#define BATCH 8
#define SEQ   1024
#define DIM   512
#define HEADS 8
#define DHEAD 64
#define SCALE 0.125f
#define LOG2E 1.4426950408889634f

#define QKV_ELEMS (BATCH*HEADS*SEQ*DHEAD)

// fp16 staging buffers (device globals: allocation-free rule)
__device__ __half g_xh [8192*512];
__device__ __half g_wqh[512*512];
__device__ __half g_wkh[512*512];
__device__ __half g_wvh[512*512];
__device__ __half g_woh[512*512];
__device__ __half g_q[QKV_ELEMS];
__device__ __half g_k[QKV_ELEMS];
__device__ __half g_v[QKV_ELEMS];
__device__ __half g_o[QKV_ELEMS];

__device__ __forceinline__ uint32_t smem_u32(const void* p) {
    uint32_t a;
    asm("{ .reg .u64 t; cvta.to.shared.u64 t, %1; cvt.u32.u64 %0, t; }" : "=r"(a) : "l"(p));
    return a;
}
__device__ __forceinline__ uint32_t h2u(float lo, float hi) {
    uint32_t u;
    asm("cvt.rn.f16x2.f32 %0, %1, %2;" : "=r"(u) : "f"(hi), "f"(lo));
    return u;
}
__device__ __forceinline__ float ex2f(float x) {
    float r;
    asm("ex2.approx.f32 %0, %1;" : "=f"(r) : "f"(x));
    return r;
}

__device__ __forceinline__ void mma16816(float c[4], const uint32_t a[4],
                                         uint32_t b0, uint32_t b1) {
    asm volatile(
        "mma.sync.aligned.m16n8k16.row.col.f32.f16.f16.f32 "
        "{%0,%1,%2,%3}, {%4,%5,%6,%7}, {%8,%9}, {%0,%1,%2,%3};\n"
        : "+f"(c[0]), "+f"(c[1]), "+f"(c[2]), "+f"(c[3])
        : "r"(a[0]), "r"(a[1]), "r"(a[2]), "r"(a[3]), "r"(b0), "r"(b1));
}

#define LDSM_X4(d0, d1, d2, d3, addr) \
    asm volatile("ldmatrix.sync.aligned.m8n8.x4.shared.b16 {%0,%1,%2,%3}, [%4];" \
                 : "=r"(d0), "=r"(d1), "=r"(d2), "=r"(d3) : "r"(addr))
#define LDSM_X4_T(d0, d1, d2, d3, addr) \
    asm volatile("ldmatrix.sync.aligned.m8n8.x4.trans.shared.b16 {%0,%1,%2,%3}, [%4];" \
                 : "=r"(d0), "=r"(d1), "=r"(d2), "=r"(d3) : "r"(addr))

#define CP16(dst, src) \
    asm volatile("cp.async.cg.shared.global [%0], [%1], 16;" :: "r"(dst), "l"(src))
#define CP_COMMIT() asm volatile("cp.async.commit_group;")
#define CP_WAIT1()  asm volatile("cp.async.wait_group 1;")

// ---------------------------------------------------------------------------
// Convert fp32 inputs -> fp16 staging. 1310720 float4s total.
// ---------------------------------------------------------------------------
__global__ __launch_bounds__(256) void conv_k(
    const float* __restrict__ x,  const float* __restrict__ wq,
    const float* __restrict__ wk, const float* __restrict__ wv,
    const float* __restrict__ wo)
{
    const uint32_t i = blockIdx.x * 256 + threadIdx.x;
    const float* src; __half* dst; uint32_t off;
    if (i < 1048576u)      { src = x;  dst = g_xh;  off = i; }
    else if (i < 1114112u) { src = wq; dst = g_wqh; off = i - 1048576u; }
    else if (i < 1179648u) { src = wk; dst = g_wkh; off = i - 1114112u; }
    else if (i < 1245184u) { src = wv; dst = g_wvh; off = i - 1179648u; }
    else                   { src = wo; dst = g_woh; off = i - 1245184u; }
    float4 v = ((const float4*)src)[off];
    ((uint2*)dst)[off] = make_uint2(h2u(v.x, v.y), h2u(v.z, v.w));
}

// ===========================================================================
// GEMM core (qkv / proj): CTA 128m x 64n, 256 thr (8 warps 4m x 2n, warp
// 32x32), k-block 64, 3-stage cp.async, 3 CTAs/SM (72KB smem, <=85 regs).
// smem: A 3x16KB @0 ; B 3x8KB @49152.
// ===========================================================================
struct GemmFrag {
    int ar0, acs, br0, bcs, wm, wn, g, tg;
    __device__ __forceinline__ GemmFrag(int lane, int wid) {
        wm = wid >> 1; wn = wid & 1;
        g = lane >> 2; tg = lane & 3;
        ar0 = wm * 32 + (lane & 15);
        acs = lane >> 4;
        br0 = wn * 32 + ((lane >> 4) << 3) + (lane & 7);
        bcs = (lane >> 3) & 1;
    }
};

// shared inner loop body (A 128x64, B 64x64 fp16 swizzled in smem)
#define GEMM_KSTEP(abuf, bbuf, acc)                                            \
    _Pragma("unroll")                                                          \
    for (int ik = 0; ik < 4; ik++) {                                           \
        uint32_t a[2][4];                                                      \
        _Pragma("unroll")                                                      \
        for (int im = 0; im < 2; im++) {                                       \
            int r = fr.ar0 + im * 16;                                          \
            uint32_t ad = (abuf) + r * 128                                     \
                        + (uint32_t)(((2 * ik + fr.acs) ^ (r & 7)) << 4);      \
            LDSM_X4(a[im][0], a[im][1], a[im][2], a[im][3], ad);               \
        }                                                                      \
        uint32_t bf[2][4];                                                     \
        _Pragma("unroll")                                                      \
        for (int nt2 = 0; nt2 < 2; nt2++) {                                    \
            int r = fr.br0 + nt2 * 16;                                         \
            uint32_t bd = (bbuf) + r * 128                                     \
                        + (uint32_t)(((2 * ik + fr.bcs) ^ (r & 7)) << 4);      \
            LDSM_X4(bf[nt2][0], bf[nt2][1], bf[nt2][2], bf[nt2][3], bd);       \
        }                                                                      \
        _Pragma("unroll")                                                      \
        for (int nt2 = 0; nt2 < 2; nt2++)                                      \
            _Pragma("unroll")                                                  \
            for (int im = 0; im < 2; im++) {                                   \
                mma16816(acc[im][2 * nt2],     a[im], bf[nt2][0], bf[nt2][1]); \
                mma16816(acc[im][2 * nt2 + 1], a[im], bf[nt2][2], bf[nt2][3]); \
            }                                                                  \
    }

// ---------------------------------------------------------------------------
// QKV: C = X @ W^T scattered to [b,h,n,d] (fp16). grid (8 heads, 64 m, 3 z).
// ---------------------------------------------------------------------------
__global__ __launch_bounds__(256, 3) void qkv_tc()
{
    extern __shared__ char dsm[];
    const uint32_t sb = smem_u32(dsm);
    const int tid = threadIdx.x, lane = tid & 31, wid = tid >> 5;
    const int h = blockIdx.x, m0 = blockIdx.y * 128, z = blockIdx.z;
    const __half* Wh = (z == 0) ? g_wqh : (z == 1) ? g_wkh : g_wvh;
    __half* out = (z == 0) ? g_q : (z == 1) ? g_k : g_v;

    const int arow = tid >> 1, acb = (tid & 1) * 4;        // A: 2 thr/row
    const int brow = tid >> 2, bcb = (tid & 3) * 2;        // B: 4 thr/row
    const __half* asrc = g_xh + (size_t)(m0 + arow) * DIM + acb * 8;
    const __half* bsrc = Wh + (size_t)(h * 64 + brow) * DIM + bcb * 8;
    const uint32_t adst = sb + arow * 128;
    const uint32_t bdst = sb + 49152 + brow * 128;

    auto fill = [&](int kt) {
        const int buf = kt % 3;
        #pragma unroll
        for (int c = 0; c < 4; c++) {
            int cc = acb + c;
            CP16(adst + buf * 16384 + ((cc ^ (arow & 7)) << 4), asrc + kt * 64 + c * 8);
        }
        #pragma unroll
        for (int c = 0; c < 2; c++) {
            int cc = bcb + c;
            CP16(bdst + buf * 8192 + ((cc ^ (brow & 7)) << 4), bsrc + kt * 64 + c * 8);
        }
    };
    fill(0); CP_COMMIT();
    fill(1); CP_COMMIT();

    const GemmFrag fr(lane, wid);
    float acc[2][4][4] = {};

    for (int kt = 0; kt < 8; kt++) {
        CP_WAIT1();
        __syncthreads();
        const uint32_t abuf = sb + (kt % 3) * 16384;
        const uint32_t bbuf = sb + 49152 + (kt % 3) * 8192;
        GEMM_KSTEP(abuf, bbuf, acc);
        if (kt < 6) fill(kt + 2);
        CP_COMMIT();
    }

    const int b = m0 >> 10, ns0 = m0 & 1023;
    #pragma unroll
    for (int im = 0; im < 2; im++) {
        int mrow = fr.wm * 32 + im * 16 + fr.g;
        __half* base = out + ((size_t)(b * HEADS + h) * SEQ + ns0 + mrow) * DHEAD;
        #pragma unroll
        for (int nt = 0; nt < 4; nt++) {
            int d = fr.wn * 32 + nt * 8 + 2 * fr.tg;
            *(uint32_t*)(base + d)             = h2u(acc[im][nt][0], acc[im][nt][1]);
            *(uint32_t*)(base + 8 * DHEAD + d) = h2u(acc[im][nt][2], acc[im][nt][3]);
        }
    }
}

// ===========================================================================
// Attention: CTA per (qt, h, b): 128 q-rows, 256 thr (8 warps x 16q).
// Q frags hoisted; K/V 3-stage cp.async; fragment double-buffering in both
// S and PV loops; PV A-frags direct from S accums; V^T via ldmatrix.trans.
// smem: Q 16KB @0; K 3x8KB @16384; V 3x8KB @40960.
// ===========================================================================
__global__ __launch_bounds__(256, 2) void attn_tc()
{
    extern __shared__ char dsm[];
    const uint32_t sb = smem_u32(dsm);
    const int tid = threadIdx.x, lane = tid & 31, wid = tid >> 5;
    const int qt = blockIdx.x, h = blockIdx.y, b = blockIdx.z;
    const __half* Qg = g_q + ((size_t)(b * HEADS + h) * SEQ + qt * 128) * DHEAD;
    const __half* Kg = g_k + ((size_t)(b * HEADS + h) * SEQ) * DHEAD;
    const __half* Vg = g_v + ((size_t)(b * HEADS + h) * SEQ) * DHEAD;

    // Q fill: 128 rows, 2 thr/row, 4 chunks each
    {
        const int row = tid >> 1, cq = (tid & 1) * 4;
        #pragma unroll
        for (int c = 0; c < 4; c++) {
            int cc = cq + c;
            CP16(sb + row * 128 + ((cc ^ (row & 7)) << 4), Qg + row * 64 + cc * 8);
        }
    }
    // KV fill: 64 rows, 4 thr/row, 2 chunks each per matrix
    const int kvrow = tid >> 2, kvcb = (tid & 3) * 2;
    auto fillKV = [&](int t) {
        const int buf = t % 3;
        #pragma unroll
        for (int c = 0; c < 2; c++) {
            int cc = kvcb + c;
            uint32_t sw = kvrow * 128 + ((cc ^ (kvrow & 7)) << 4);
            CP16(sb + 16384 + buf * 8192 + sw, Kg + (size_t)(t * 64 + kvrow) * 64 + cc * 8);
            CP16(sb + 40960 + buf * 8192 + sw, Vg + (size_t)(t * 64 + kvrow) * 64 + cc * 8);
        }
    };
    fillKV(0); CP_COMMIT();      // group0: Q + KV0
    fillKV(1); CP_COMMIT();      // group1: KV1
    CP_WAIT1();                  // group0 done
    __syncthreads();

    const int g = lane >> 2, tg = lane & 3;
    uint32_t qf[4][4];
    {
        int r = wid * 16 + (lane & 15);
        int cs = lane >> 4;
        #pragma unroll
        for (int ik = 0; ik < 4; ik++) {
            uint32_t ad = sb + r * 128 + (uint32_t)(((2 * ik + cs) ^ (r & 7)) << 4);
            LDSM_X4(qf[ik][0], qf[ik][1], qf[ik][2], qf[ik][3], ad);
        }
    }

    const int br0 = ((lane >> 4) << 3) + (lane & 7);       // K: rows = j
    const int bcs = (lane >> 3) & 1;
    const int vr0 = ((lane >> 3) & 1) * 8 + (lane & 7);    // V trans: rows = j
    const int vcs = lane >> 4;

    auto ldK = [&](uint32_t kb, int ik, int nt2, uint32_t f[4]) {
        int r = nt2 * 16 + br0;
        uint32_t bd = kb + r * 128 + (uint32_t)(((2 * ik + bcs) ^ (r & 7)) << 4);
        LDSM_X4(f[0], f[1], f[2], f[3], bd);
    };
    auto ldV = [&](uint32_t vb, int jk, int dt2, uint32_t f[4]) {
        int r = jk * 16 + vr0;
        uint32_t bd = vb + r * 128 + (uint32_t)(((2 * dt2 + vcs) ^ (r & 7)) << 4);
        LDSM_X4_T(f[0], f[1], f[2], f[3], bd);
    };

    float oc[8][4] = {};
    float rsum0 = 0.f, rsum1 = 0.f;
    const float scl2e = SCALE * LOG2E;
    const float lo = 1e-6f * LOG2E, hi = LOG2E;

    for (int t = 0; t < 16; t++) {
        if (t) { CP_WAIT1(); __syncthreads(); }
        const uint32_t kb = sb + 16384 + (t % 3) * 8192;
        const uint32_t vb = sb + 40960 + (t % 3) * 8192;

        // ---- S = Q K^T, pipelined over flattened (ik, nt2) ----
        float sc[8][4] = {};
        uint32_t kf[2][4];
        ldK(kb, 0, 0, kf[0]);
        #pragma unroll
        for (int s = 0; s < 16; s++) {
            const int ik = s >> 2, nt2 = s & 3, cur = s & 1;
            if (s < 15) ldK(kb, (s + 1) >> 2, (s + 1) & 3, kf[cur ^ 1]);
            mma16816(sc[2 * nt2],     qf[ik], kf[cur][0], kf[cur][1]);
            mma16816(sc[2 * nt2 + 1], qf[ik], kf[cur][2], kf[cur][3]);
        }

        // ---- P = 2^(clip(S*scale*log2e)), running row sums ----
        #pragma unroll
        for (int in = 0; in < 8; in++) {
            #pragma unroll
            for (int r = 0; r < 4; r++)
                sc[in][r] = ex2f(fminf(fmaxf(sc[in][r] * scl2e, lo), hi));
            rsum0 += sc[in][0] + sc[in][1];
            rsum1 += sc[in][2] + sc[in][3];
        }

        // ---- O += P V, pipelined over flattened (jk, dt2) ----
        uint32_t vf[2][4];
        uint32_t a[4];
        ldV(vb, 0, 0, vf[0]);
        #pragma unroll
        for (int s = 0; s < 16; s++) {
            const int jk = s >> 2, dt2 = s & 3, cur = s & 1;
            if (dt2 == 0) {
                a[0] = h2u(sc[2 * jk][0],     sc[2 * jk][1]);
                a[1] = h2u(sc[2 * jk][2],     sc[2 * jk][3]);
                a[2] = h2u(sc[2 * jk + 1][0], sc[2 * jk + 1][1]);
                a[3] = h2u(sc[2 * jk + 1][2], sc[2 * jk + 1][3]);
            }
            if (s < 15) ldV(vb, (s + 1) >> 2, (s + 1) & 3, vf[cur ^ 1]);
            mma16816(oc[2 * dt2],     a, vf[cur][0], vf[cur][1]);
            mma16816(oc[2 * dt2 + 1], a, vf[cur][2], vf[cur][3]);
        }
        if (t < 14) fillKV(t + 2);
        CP_COMMIT();
    }

    rsum0 += __shfl_xor_sync(0xffffffffu, rsum0, 1);
    rsum0 += __shfl_xor_sync(0xffffffffu, rsum0, 2);
    rsum1 += __shfl_xor_sync(0xffffffffu, rsum1, 1);
    rsum1 += __shfl_xor_sync(0xffffffffu, rsum1, 2);
    const float inv0 = 1.0f / rsum0, inv1 = 1.0f / rsum1;

    __half* ob = g_o + ((size_t)(b * HEADS + h) * SEQ + qt * 128 + wid * 16 + g) * DHEAD;
    #pragma unroll
    for (int dt = 0; dt < 8; dt++) {
        int d = dt * 8 + 2 * tg;
        *(uint32_t*)(ob + d)             = h2u(oc[dt][0] * inv0, oc[dt][1] * inv0);
        *(uint32_t*)(ob + 8 * DHEAD + d) = h2u(oc[dt][2] * inv1, oc[dt][3] * inv1);
    }
}

// ---------------------------------------------------------------------------
// Out-proj: out = concat(g_o) @ Wo^T + bo (fp32). CTA 128m x 64n, grid (8,64).
// A gathered from [b,h,n,d] (k-block == one head).
// ---------------------------------------------------------------------------
__global__ __launch_bounds__(256, 3) void proj_tc(
    const float* __restrict__ bo, float* __restrict__ outp)
{
    extern __shared__ char dsm[];
    const uint32_t sb = smem_u32(dsm);
    const int tid = threadIdx.x, lane = tid & 31, wid = tid >> 5;
    const int nblk = blockIdx.x, m0 = blockIdx.y * 128;
    const int b = m0 >> 10, ns0 = m0 & 1023;

    const int arow = tid >> 1, acb = (tid & 1) * 4;
    const int brow = tid >> 2, bcb = (tid & 3) * 2;
    const __half* bsrc = g_woh + (size_t)(nblk * 64 + brow) * DIM + bcb * 8;
    const uint32_t adst = sb + arow * 128;
    const uint32_t bdst = sb + 49152 + brow * 128;

    auto fill = [&](int kt) {
        const int buf = kt % 3;
        const __half* asrc = g_o + ((size_t)(b * HEADS + kt) * SEQ + ns0 + arow) * DHEAD + acb * 8;
        #pragma unroll
        for (int c = 0; c < 4; c++) {
            int cc = acb + c;
            CP16(adst + buf * 16384 + ((cc ^ (arow & 7)) << 4), asrc + c * 8);
        }
        #pragma unroll
        for (int c = 0; c < 2; c++) {
            int cc = bcb + c;
            CP16(bdst + buf * 8192 + ((cc ^ (brow & 7)) << 4), bsrc + kt * 64 + c * 8);
        }
    };
    fill(0); CP_COMMIT();
    fill(1); CP_COMMIT();

    const GemmFrag fr(lane, wid);
    float acc[2][4][4] = {};

    for (int kt = 0; kt < 8; kt++) {
        CP_WAIT1();
        __syncthreads();
        const uint32_t abuf = sb + (kt % 3) * 16384;
        const uint32_t bbuf = sb + 49152 + (kt % 3) * 8192;
        GEMM_KSTEP(abuf, bbuf, acc);
        if (kt < 6) fill(kt + 2);
        CP_COMMIT();
    }

    #pragma unroll
    for (int im = 0; im < 2; im++) {
        int mrow = m0 + fr.wm * 32 + im * 16 + fr.g;
        #pragma unroll
        for (int nt = 0; nt < 4; nt++) {
            int n = nblk * 64 + fr.wn * 32 + nt * 8 + 2 * fr.tg;
            float2 bias = *(const float2*)(bo + n);
            float* op = outp + (size_t)mrow * DIM + n;
            *(float2*)op = make_float2(acc[im][nt][0] + bias.x, acc[im][nt][1] + bias.y);
            *(float2*)(op + 8 * DIM) = make_float2(acc[im][nt][2] + bias.x,
                                                   acc[im][nt][3] + bias.y);
        }
    }
}

// ---------------------------------------------------------------------------
extern "C" void kernel_launch(void* const* d_in, const int* in_sizes, int n_in,
                              void* d_out, int out_size)
{
    (void)in_sizes; (void)n_in; (void)out_size;
    const float* x  = (const float*)d_in[0];
    const float* wq = (const float*)d_in[1];
    const float* wk = (const float*)d_in[2];
    const float* wv = (const float*)d_in[3];
    const float* wo = (const float*)d_in[4];
    const float* bo = (const float*)d_in[5];
    float* out = (float*)d_out;

    cudaFuncSetAttribute(qkv_tc,  cudaFuncAttributeMaxDynamicSharedMemorySize, 73728);
    cudaFuncSetAttribute(attn_tc, cudaFuncAttributeMaxDynamicSharedMemorySize, 65536);
    cudaFuncSetAttribute(proj_tc, cudaFuncAttributeMaxDynamicSharedMemorySize, 73728);

    conv_k<<<5120, 256>>>(x, wq, wk, wv, wo);
    qkv_tc<<<dim3(HEADS, 64, 3), 256, 73728>>>();
    attn_tc<<<dim3(SEQ / 128, HEADS, BATCH), 256, 65536>>>();
    proj_tc<<<dim3(8, 64), 256, 73728>>>(bo, out);
}

// round 10
// speedup vs baseline: 1.3344x; 1.0173x over previous
#include <cuda_runtime.h>
#include <cuda_fp16.h>
#include <cstdint>

#define BATCH 8
#define SEQ   1024
#define DIM   512
#define HEADS 8
#define DHEAD 64
#define SCALE 0.125f
#define LOG2E 1.4426950408889634f
#define ONESX2 0x3C003C00u

#define QKV_ELEMS (BATCH*HEADS*SEQ*DHEAD)

// fp16 staging buffers (device globals: allocation-free rule)
__device__ __half g_xh [8192*512];
__device__ __half g_wqh[512*512];
__device__ __half g_wkh[512*512];
__device__ __half g_wvh[512*512];
__device__ __half g_woh[512*512];
__device__ __half g_q[QKV_ELEMS];
__device__ __half g_k[QKV_ELEMS];
__device__ __half g_v[QKV_ELEMS];
__device__ __half g_o[QKV_ELEMS];

__device__ __forceinline__ uint32_t smem_u32(const void* p) {
    uint32_t a;
    asm("{ .reg .u64 t; cvta.to.shared.u64 t, %1; cvt.u32.u64 %0, t; }" : "=r"(a) : "l"(p));
    return a;
}
__device__ __forceinline__ uint32_t h2u(float lo, float hi) {
    uint32_t u;
    asm("cvt.rn.f16x2.f32 %0, %1, %2;" : "=r"(u) : "f"(hi), "f"(lo));
    return u;
}
__device__ __forceinline__ uint32_t ex2h2(uint32_t x) {
    uint32_t r;
    asm("ex2.approx.f16x2 %0, %1;" : "=r"(r) : "r"(x));
    return r;
}

__device__ __forceinline__ void mma16816(float c[4], const uint32_t a[4],
                                         uint32_t b0, uint32_t b1) {
    asm volatile(
        "mma.sync.aligned.m16n8k16.row.col.f32.f16.f16.f32 "
        "{%0,%1,%2,%3}, {%4,%5,%6,%7}, {%8,%9}, {%0,%1,%2,%3};\n"
        : "+f"(c[0]), "+f"(c[1]), "+f"(c[2]), "+f"(c[3])
        : "r"(a[0]), "r"(a[1]), "r"(a[2]), "r"(a[3]), "r"(b0), "r"(b1));
}

#define LDSM_X4(d0, d1, d2, d3, addr) \
    asm volatile("ldmatrix.sync.aligned.m8n8.x4.shared.b16 {%0,%1,%2,%3}, [%4];" \
                 : "=r"(d0), "=r"(d1), "=r"(d2), "=r"(d3) : "r"(addr))
#define LDSM_X4_T(d0, d1, d2, d3, addr) \
    asm volatile("ldmatrix.sync.aligned.m8n8.x4.trans.shared.b16 {%0,%1,%2,%3}, [%4];" \
                 : "=r"(d0), "=r"(d1), "=r"(d2), "=r"(d3) : "r"(addr))

#define CP16(dst, src) \
    asm volatile("cp.async.cg.shared.global [%0], [%1], 16;" :: "r"(dst), "l"(src))
#define CP_COMMIT() asm volatile("cp.async.commit_group;")
#define CP_WAIT1()  asm volatile("cp.async.wait_group 1;")

// ---------------------------------------------------------------------------
// Convert fp32 inputs -> fp16 staging. 1310720 float4s total.
// ---------------------------------------------------------------------------
__global__ __launch_bounds__(256) void conv_k(
    const float* __restrict__ x,  const float* __restrict__ wq,
    const float* __restrict__ wk, const float* __restrict__ wv,
    const float* __restrict__ wo)
{
    const uint32_t i = blockIdx.x * 256 + threadIdx.x;
    const float* src; __half* dst; uint32_t off;
    if (i < 1048576u)      { src = x;  dst = g_xh;  off = i; }
    else if (i < 1114112u) { src = wq; dst = g_wqh; off = i - 1048576u; }
    else if (i < 1179648u) { src = wk; dst = g_wkh; off = i - 1114112u; }
    else if (i < 1245184u) { src = wv; dst = g_wvh; off = i - 1179648u; }
    else                   { src = wo; dst = g_woh; off = i - 1245184u; }
    float4 v = ((const float4*)src)[off];
    ((uint2*)dst)[off] = make_uint2(h2u(v.x, v.y), h2u(v.z, v.w));
}

// ===========================================================================
// GEMM core (qkv / proj): CTA 128m x 64n, 256 thr (8 warps 4m x 2n, warp
// 32x32), k-block 64, 3-stage cp.async, 3 CTAs/SM (72KB smem, <=85 regs).
// smem: A 3x16KB @0 ; B 3x8KB @49152.
// ===========================================================================
struct GemmFrag {
    int ar0, acs, br0, bcs, wm, wn, g, tg;
    __device__ __forceinline__ GemmFrag(int lane, int wid) {
        wm = wid >> 1; wn = wid & 1;
        g = lane >> 2; tg = lane & 3;
        ar0 = wm * 32 + (lane & 15);
        acs = lane >> 4;
        br0 = wn * 32 + ((lane >> 4) << 3) + (lane & 7);
        bcs = (lane >> 3) & 1;
    }
};

#define GEMM_KSTEP(abuf, bbuf, acc)                                            \
    _Pragma("unroll")                                                          \
    for (int ik = 0; ik < 4; ik++) {                                           \
        uint32_t a[2][4];                                                      \
        _Pragma("unroll")                                                      \
        for (int im = 0; im < 2; im++) {                                       \
            int r = fr.ar0 + im * 16;                                          \
            uint32_t ad = (abuf) + r * 128                                     \
                        + (uint32_t)(((2 * ik + fr.acs) ^ (r & 7)) << 4);      \
            LDSM_X4(a[im][0], a[im][1], a[im][2], a[im][3], ad);               \
        }                                                                      \
        uint32_t bf[2][4];                                                     \
        _Pragma("unroll")                                                      \
        for (int nt2 = 0; nt2 < 2; nt2++) {                                    \
            int r = fr.br0 + nt2 * 16;                                         \
            uint32_t bd = (bbuf) + r * 128                                     \
                        + (uint32_t)(((2 * ik + fr.bcs) ^ (r & 7)) << 4);      \
            LDSM_X4(bf[nt2][0], bf[nt2][1], bf[nt2][2], bf[nt2][3], bd);       \
        }                                                                      \
        _Pragma("unroll")                                                      \
        for (int nt2 = 0; nt2 < 2; nt2++)                                      \
            _Pragma("unroll")                                                  \
            for (int im = 0; im < 2; im++) {                                   \
                mma16816(acc[im][2 * nt2],     a[im], bf[nt2][0], bf[nt2][1]); \
                mma16816(acc[im][2 * nt2 + 1], a[im], bf[nt2][2], bf[nt2][3]); \
            }                                                                  \
    }

// ---------------------------------------------------------------------------
// QKV: C = X @ W^T scattered to [b,h,n,d] (fp16). grid (8 heads, 64 m, 3 z).
// ---------------------------------------------------------------------------
__global__ __launch_bounds__(256, 3) void qkv_tc()
{
    extern __shared__ char dsm[];
    const uint32_t sb = smem_u32(dsm);
    const int tid = threadIdx.x, lane = tid & 31, wid = tid >> 5;
    const int h = blockIdx.x, m0 = blockIdx.y * 128, z = blockIdx.z;
    const __half* Wh = (z == 0) ? g_wqh : (z == 1) ? g_wkh : g_wvh;
    __half* out = (z == 0) ? g_q : (z == 1) ? g_k : g_v;

    const int arow = tid >> 1, acb = (tid & 1) * 4;
    const int brow = tid >> 2, bcb = (tid & 3) * 2;
    const __half* asrc = g_xh + (size_t)(m0 + arow) * DIM + acb * 8;
    const __half* bsrc = Wh + (size_t)(h * 64 + brow) * DIM + bcb * 8;
    const uint32_t adst = sb + arow * 128;
    const uint32_t bdst = sb + 49152 + brow * 128;

    auto fill = [&](int kt) {
        const int buf = kt % 3;
        #pragma unroll
        for (int c = 0; c < 4; c++) {
            int cc = acb + c;
            CP16(adst + buf * 16384 + ((cc ^ (arow & 7)) << 4), asrc + kt * 64 + c * 8);
        }
        #pragma unroll
        for (int c = 0; c < 2; c++) {
            int cc = bcb + c;
            CP16(bdst + buf * 8192 + ((cc ^ (brow & 7)) << 4), bsrc + kt * 64 + c * 8);
        }
    };
    fill(0); CP_COMMIT();
    fill(1); CP_COMMIT();

    const GemmFrag fr(lane, wid);
    float acc[2][4][4] = {};

    for (int kt = 0; kt < 8; kt++) {
        CP_WAIT1();
        __syncthreads();
        const uint32_t abuf = sb + (kt % 3) * 16384;
        const uint32_t bbuf = sb + 49152 + (kt % 3) * 8192;
        GEMM_KSTEP(abuf, bbuf, acc);
        if (kt < 6) fill(kt + 2);
        CP_COMMIT();
    }

    const int b = m0 >> 10, ns0 = m0 & 1023;
    #pragma unroll
    for (int im = 0; im < 2; im++) {
        int mrow = fr.wm * 32 + im * 16 + fr.g;
        __half* base = out + ((size_t)(b * HEADS + h) * SEQ + ns0 + mrow) * DHEAD;
        #pragma unroll
        for (int nt = 0; nt < 4; nt++) {
            int d = fr.wn * 32 + nt * 8 + 2 * fr.tg;
            *(uint32_t*)(base + d)             = h2u(acc[im][nt][0], acc[im][nt][1]);
            *(uint32_t*)(base + 8 * DHEAD + d) = h2u(acc[im][nt][2], acc[im][nt][3]);
        }
    }
}

// ===========================================================================
// Attention: CTA per (qt, h, b): 128 q-rows, 256 thr (8 warps x 16q).
// f16x2 softmax (ex2.approx.f16x2), P packed directly as PV A-operands,
// row sums via ones-MMA. K/V 3-stage cp.async, fragment double-buffering.
// smem: Q 16KB @0; K 3x8KB @16384; V 3x8KB @40960.
// ===========================================================================
__global__ __launch_bounds__(256, 2) void attn_tc()
{
    extern __shared__ char dsm[];
    const uint32_t sb = smem_u32(dsm);
    const int tid = threadIdx.x, lane = tid & 31, wid = tid >> 5;
    const int qt = blockIdx.x, h = blockIdx.y, b = blockIdx.z;
    const __half* Qg = g_q + ((size_t)(b * HEADS + h) * SEQ + qt * 128) * DHEAD;
    const __half* Kg = g_k + ((size_t)(b * HEADS + h) * SEQ) * DHEAD;
    const __half* Vg = g_v + ((size_t)(b * HEADS + h) * SEQ) * DHEAD;

    // Q fill: 128 rows, 2 thr/row, 4 chunks each
    {
        const int row = tid >> 1, cq = (tid & 1) * 4;
        #pragma unroll
        for (int c = 0; c < 4; c++) {
            int cc = cq + c;
            CP16(sb + row * 128 + ((cc ^ (row & 7)) << 4), Qg + row * 64 + cc * 8);
        }
    }
    // KV fill: 64 rows, 4 thr/row, 2 chunks each per matrix
    const int kvrow = tid >> 2, kvcb = (tid & 3) * 2;
    auto fillKV = [&](int t) {
        const int buf = t % 3;
        #pragma unroll
        for (int c = 0; c < 2; c++) {
            int cc = kvcb + c;
            uint32_t sw = kvrow * 128 + ((cc ^ (kvrow & 7)) << 4);
            CP16(sb + 16384 + buf * 8192 + sw, Kg + (size_t)(t * 64 + kvrow) * 64 + cc * 8);
            CP16(sb + 40960 + buf * 8192 + sw, Vg + (size_t)(t * 64 + kvrow) * 64 + cc * 8);
        }
    };
    fillKV(0); CP_COMMIT();      // group0: Q + KV0
    fillKV(1); CP_COMMIT();      // group1: KV1
    CP_WAIT1();                  // group0 done
    __syncthreads();

    const int g = lane >> 2, tg = lane & 3;
    uint32_t qf[4][4];
    {
        int r = wid * 16 + (lane & 15);
        int cs = lane >> 4;
        #pragma unroll
        for (int ik = 0; ik < 4; ik++) {
            uint32_t ad = sb + r * 128 + (uint32_t)(((2 * ik + cs) ^ (r & 7)) << 4);
            LDSM_X4(qf[ik][0], qf[ik][1], qf[ik][2], qf[ik][3], ad);
        }
    }

    const int br0 = ((lane >> 4) << 3) + (lane & 7);       // K: rows = j
    const int bcs = (lane >> 3) & 1;
    const int vr0 = ((lane >> 3) & 1) * 8 + (lane & 7);    // V trans: rows = j
    const int vcs = lane >> 4;

    auto ldK = [&](uint32_t kb, int ik, int nt2, uint32_t f[4]) {
        int r = nt2 * 16 + br0;
        uint32_t bd = kb + r * 128 + (uint32_t)(((2 * ik + bcs) ^ (r & 7)) << 4);
        LDSM_X4(f[0], f[1], f[2], f[3], bd);
    };
    auto ldV = [&](uint32_t vb, int jk, int dt2, uint32_t f[4]) {
        int r = jk * 16 + vr0;
        uint32_t bd = vb + r * 128 + (uint32_t)(((2 * dt2 + vcs) ^ (r & 7)) << 4);
        LDSM_X4_T(f[0], f[1], f[2], f[3], bd);
    };

    float oc[8][4] = {};
    float rs[4] = {};                    // row-sum MMA accumulator
    const float scl2e = SCALE * LOG2E;
    const float lo = 1e-6f * LOG2E, hi = LOG2E;

    for (int t = 0; t < 16; t++) {
        if (t) { CP_WAIT1(); __syncthreads(); }
        const uint32_t kb = sb + 16384 + (t % 3) * 8192;
        const uint32_t vb = sb + 40960 + (t % 3) * 8192;

        // ---- S = Q K^T, pipelined over flattened (ik, nt2) ----
        float sc[8][4] = {};
        uint32_t kf[2][4];
        ldK(kb, 0, 0, kf[0]);
        #pragma unroll
        for (int s = 0; s < 16; s++) {
            const int ik = s >> 2, nt2 = s & 3, cur = s & 1;
            if (s < 15) ldK(kb, (s + 1) >> 2, (s + 1) & 3, kf[cur ^ 1]);
            mma16816(sc[2 * nt2],     qf[ik], kf[cur][0], kf[cur][1]);
            mma16816(sc[2 * nt2 + 1], qf[ik], kf[cur][2], kf[cur][3]);
        }

        // ---- P = 2^(clip(S*scale*log2e)) packed f16x2 ----
        uint32_t p[8][2];
        #pragma unroll
        for (int in = 0; in < 8; in++) {
            float x0 = fminf(fmaxf(sc[in][0] * scl2e, lo), hi);
            float x1 = fminf(fmaxf(sc[in][1] * scl2e, lo), hi);
            float x2 = fminf(fmaxf(sc[in][2] * scl2e, lo), hi);
            float x3 = fminf(fmaxf(sc[in][3] * scl2e, lo), hi);
            p[in][0] = ex2h2(h2u(x0, x1));
            p[in][1] = ex2h2(h2u(x2, x3));
        }

        // ---- O += P V (A frags = packed P); row sums via ones-MMA ----
        uint32_t vf[2][4];
        uint32_t a[4];
        ldV(vb, 0, 0, vf[0]);
        #pragma unroll
        for (int s = 0; s < 16; s++) {
            const int jk = s >> 2, dt2 = s & 3, cur = s & 1;
            if (dt2 == 0) {
                a[0] = p[2 * jk][0];
                a[1] = p[2 * jk][1];
                a[2] = p[2 * jk + 1][0];
                a[3] = p[2 * jk + 1][1];
                mma16816(rs, a, ONESX2, ONESX2);
            }
            if (s < 15) ldV(vb, (s + 1) >> 2, (s + 1) & 3, vf[cur ^ 1]);
            mma16816(oc[2 * dt2],     a, vf[cur][0], vf[cur][1]);
            mma16816(oc[2 * dt2 + 1], a, vf[cur][2], vf[cur][3]);
        }
        if (t < 14) fillKV(t + 2);
        CP_COMMIT();
    }

    const float inv0 = 1.0f / rs[0], inv1 = 1.0f / rs[2];

    __half* ob = g_o + ((size_t)(b * HEADS + h) * SEQ + qt * 128 + wid * 16 + g) * DHEAD;
    #pragma unroll
    for (int dt = 0; dt < 8; dt++) {
        int d = dt * 8 + 2 * tg;
        *(uint32_t*)(ob + d)             = h2u(oc[dt][0] * inv0, oc[dt][1] * inv0);
        *(uint32_t*)(ob + 8 * DHEAD + d) = h2u(oc[dt][2] * inv1, oc[dt][3] * inv1);
    }
}

// ---------------------------------------------------------------------------
// Out-proj: out = concat(g_o) @ Wo^T + bo (fp32). CTA 128m x 64n, grid (8,64).
// A gathered from [b,h,n,d] (k-block == one head).
// ---------------------------------------------------------------------------
__global__ __launch_bounds__(256, 3) void proj_tc(
    const float* __restrict__ bo, float* __restrict__ outp)
{
    extern __shared__ char dsm[];
    const uint32_t sb = smem_u32(dsm);
    const int tid = threadIdx.x, lane = tid & 31, wid = tid >> 5;
    const int nblk = blockIdx.x, m0 = blockIdx.y * 128;
    const int b = m0 >> 10, ns0 = m0 & 1023;

    const int arow = tid >> 1, acb = (tid & 1) * 4;
    const int brow = tid >> 2, bcb = (tid & 3) * 2;
    const __half* bsrc = g_woh + (size_t)(nblk * 64 + brow) * DIM + bcb * 8;
    const uint32_t adst = sb + arow * 128;
    const uint32_t bdst = sb + 49152 + brow * 128;

    auto fill = [&](int kt) {
        const int buf = kt % 3;
        const __half* asrc = g_o + ((size_t)(b * HEADS + kt) * SEQ + ns0 + arow) * DHEAD + acb * 8;
        #pragma unroll
        for (int c = 0; c < 4; c++) {
            int cc = acb + c;
            CP16(adst + buf * 16384 + ((cc ^ (arow & 7)) << 4), asrc + c * 8);
        }
        #pragma unroll
        for (int c = 0; c < 2; c++) {
            int cc = bcb + c;
            CP16(bdst + buf * 8192 + ((cc ^ (brow & 7)) << 4), bsrc + kt * 64 + c * 8);
        }
    };
    fill(0); CP_COMMIT();
    fill(1); CP_COMMIT();

    const GemmFrag fr(lane, wid);
    float acc[2][4][4] = {};

    for (int kt = 0; kt < 8; kt++) {
        CP_WAIT1();
        __syncthreads();
        const uint32_t abuf = sb + (kt % 3) * 16384;
        const uint32_t bbuf = sb + 49152 + (kt % 3) * 8192;
        GEMM_KSTEP(abuf, bbuf, acc);
        if (kt < 6) fill(kt + 2);
        CP_COMMIT();
    }

    #pragma unroll
    for (int im = 0; im < 2; im++) {
        int mrow = m0 + fr.wm * 32 + im * 16 + fr.g;
        #pragma unroll
        for (int nt = 0; nt < 4; nt++) {
            int n = nblk * 64 + fr.wn * 32 + nt * 8 + 2 * fr.tg;
            float2 bias = *(const float2*)(bo + n);
            float* op = outp + (size_t)mrow * DIM + n;
            *(float2*)op = make_float2(acc[im][nt][0] + bias.x, acc[im][nt][1] + bias.y);
            *(float2*)(op + 8 * DIM) = make_float2(acc[im][nt][2] + bias.x,
                                                   acc[im][nt][3] + bias.y);
        }
    }
}

// ---------------------------------------------------------------------------
extern "C" void kernel_launch(void* const* d_in, const int* in_sizes, int n_in,
                              void* d_out, int out_size)
{
    (void)in_sizes; (void)n_in; (void)out_size;
    const float* x  = (const float*)d_in[0];
    const float* wq = (const float*)d_in[1];
    const float* wk = (const float*)d_in[2];
    const float* wv = (const float*)d_in[3];
    const float* wo = (const float*)d_in[4];
    const float* bo = (const float*)d_in[5];
    float* out = (float*)d_out;

    cudaFuncSetAttribute(qkv_tc,  cudaFuncAttributeMaxDynamicSharedMemorySize, 73728);
    cudaFuncSetAttribute(attn_tc, cudaFuncAttributeMaxDynamicSharedMemorySize, 65536);
    cudaFuncSetAttribute(proj_tc, cudaFuncAttributeMaxDynamicSharedMemorySize, 73728);

    conv_k<<<5120, 256>>>(x, wq, wk, wv, wo);
    qkv_tc<<<dim3(HEADS, 64, 3), 256, 73728>>>();
    attn_tc<<<dim3(SEQ / 128, HEADS, BATCH), 256, 65536>>>();
    proj_tc<<<dim3(8, 64), 256, 73728>>>(bo, out);
}

// round 11
// speedup vs baseline: 1.3403x; 1.0044x over previous
#include <cuda_runtime.h>
#include <cuda_fp16.h>
#include <cstdint>

#define BATCH 8
#define SEQ   1024
#define DIM   512
#define HEADS 8
#define DHEAD 64
#define SCALE 0.125f
#define LOG2E 1.4426950408889634f
#define ONESX2 0x3C003C00u

#define QKV_ELEMS (BATCH*HEADS*SEQ*DHEAD)

// fp16 staging buffers (device globals: allocation-free rule)
__device__ __half g_xh [8192*512];
__device__ __half g_wqh[512*512];
__device__ __half g_wkh[512*512];
__device__ __half g_wvh[512*512];
__device__ __half g_woh[512*512];
__device__ __half g_q[QKV_ELEMS];
__device__ __half g_k[QKV_ELEMS];
__device__ __half g_v[QKV_ELEMS];
__device__ __half g_o[QKV_ELEMS];

__device__ __forceinline__ uint32_t smem_u32(const void* p) {
    uint32_t a;
    asm("{ .reg .u64 t; cvta.to.shared.u64 t, %1; cvt.u32.u64 %0, t; }" : "=r"(a) : "l"(p));
    return a;
}
__device__ __forceinline__ uint32_t h2u(float lo, float hi) {
    uint32_t u;
    asm("cvt.rn.f16x2.f32 %0, %1, %2;" : "=r"(u) : "f"(hi), "f"(lo));
    return u;
}
__device__ __forceinline__ uint32_t ex2h2(uint32_t x) {
    uint32_t r;
    asm("ex2.approx.f16x2 %0, %1;" : "=r"(r) : "r"(x));
    return r;
}

__device__ __forceinline__ void mma16816(float c[4], const uint32_t a[4],
                                         uint32_t b0, uint32_t b1) {
    asm volatile(
        "mma.sync.aligned.m16n8k16.row.col.f32.f16.f16.f32 "
        "{%0,%1,%2,%3}, {%4,%5,%6,%7}, {%8,%9}, {%0,%1,%2,%3};\n"
        : "+f"(c[0]), "+f"(c[1]), "+f"(c[2]), "+f"(c[3])
        : "r"(a[0]), "r"(a[1]), "r"(a[2]), "r"(a[3]), "r"(b0), "r"(b1));
}

#define LDSM_X4(d0, d1, d2, d3, addr) \
    asm volatile("ldmatrix.sync.aligned.m8n8.x4.shared.b16 {%0,%1,%2,%3}, [%4];" \
                 : "=r"(d0), "=r"(d1), "=r"(d2), "=r"(d3) : "r"(addr))
#define LDSM_X4_T(d0, d1, d2, d3, addr) \
    asm volatile("ldmatrix.sync.aligned.m8n8.x4.trans.shared.b16 {%0,%1,%2,%3}, [%4];" \
                 : "=r"(d0), "=r"(d1), "=r"(d2), "=r"(d3) : "r"(addr))

#define CP16(dst, src) \
    asm volatile("cp.async.cg.shared.global [%0], [%1], 16;" :: "r"(dst), "l"(src))
#define CP_COMMIT() asm volatile("cp.async.commit_group;")
#define CP_WAIT1()  asm volatile("cp.async.wait_group 1;")

// ---------------------------------------------------------------------------
// Convert fp32 inputs -> fp16 staging. 1310720 float4s total.
// ---------------------------------------------------------------------------
__global__ __launch_bounds__(256) void conv_k(
    const float* __restrict__ x,  const float* __restrict__ wq,
    const float* __restrict__ wk, const float* __restrict__ wv,
    const float* __restrict__ wo)
{
    const uint32_t i = blockIdx.x * 256 + threadIdx.x;
    const float* src; __half* dst; uint32_t off;
    if (i < 1048576u)      { src = x;  dst = g_xh;  off = i; }
    else if (i < 1114112u) { src = wq; dst = g_wqh; off = i - 1048576u; }
    else if (i < 1179648u) { src = wk; dst = g_wkh; off = i - 1114112u; }
    else if (i < 1245184u) { src = wv; dst = g_wvh; off = i - 1179648u; }
    else                   { src = wo; dst = g_woh; off = i - 1245184u; }
    float4 v = ((const float4*)src)[off];
    ((uint2*)dst)[off] = make_uint2(h2u(v.x, v.y), h2u(v.z, v.w));
}

// ===========================================================================
// GEMM core (qkv / proj): CTA 128m x 64n, 256 thr (8 warps 4m x 2n, warp
// 32x32), k-block 64, 3-stage cp.async, 3 CTAs/SM (72KB smem, <=85 regs).
// ===========================================================================
struct GemmFrag {
    int ar0, acs, br0, bcs, wm, wn, g, tg;
    __device__ __forceinline__ GemmFrag(int lane, int wid) {
        wm = wid >> 1; wn = wid & 1;
        g = lane >> 2; tg = lane & 3;
        ar0 = wm * 32 + (lane & 15);
        acs = lane >> 4;
        br0 = wn * 32 + ((lane >> 4) << 3) + (lane & 7);
        bcs = (lane >> 3) & 1;
    }
};

#define GEMM_KSTEP(abuf, bbuf, acc)                                            \
    _Pragma("unroll")                                                          \
    for (int ik = 0; ik < 4; ik++) {                                           \
        uint32_t a[2][4];                                                      \
        _Pragma("unroll")                                                      \
        for (int im = 0; im < 2; im++) {                                       \
            int r = fr.ar0 + im * 16;                                          \
            uint32_t ad = (abuf) + r * 128                                     \
                        + (uint32_t)(((2 * ik + fr.acs) ^ (r & 7)) << 4);      \
            LDSM_X4(a[im][0], a[im][1], a[im][2], a[im][3], ad);               \
        }                                                                      \
        uint32_t bf[2][4];                                                     \
        _Pragma("unroll")                                                      \
        for (int nt2 = 0; nt2 < 2; nt2++) {                                    \
            int r = fr.br0 + nt2 * 16;                                         \
            uint32_t bd = (bbuf) + r * 128                                     \
                        + (uint32_t)(((2 * ik + fr.bcs) ^ (r & 7)) << 4);      \
            LDSM_X4(bf[nt2][0], bf[nt2][1], bf[nt2][2], bf[nt2][3], bd);       \
        }                                                                      \
        _Pragma("unroll")                                                      \
        for (int nt2 = 0; nt2 < 2; nt2++)                                      \
            _Pragma("unroll")                                                  \
            for (int im = 0; im < 2; im++) {                                   \
                mma16816(acc[im][2 * nt2],     a[im], bf[nt2][0], bf[nt2][1]); \
                mma16816(acc[im][2 * nt2 + 1], a[im], bf[nt2][2], bf[nt2][3]); \
            }                                                                  \
    }

// ---------------------------------------------------------------------------
// QKV: C = X @ W^T scattered to [b,h,n,d] (fp16). grid (8 heads, 64 m, 3 z).
// ---------------------------------------------------------------------------
__global__ __launch_bounds__(256, 3) void qkv_tc()
{
    extern __shared__ char dsm[];
    const uint32_t sb = smem_u32(dsm);
    const int tid = threadIdx.x, lane = tid & 31, wid = tid >> 5;
    const int h = blockIdx.x, m0 = blockIdx.y * 128, z = blockIdx.z;
    const __half* Wh = (z == 0) ? g_wqh : (z == 1) ? g_wkh : g_wvh;
    __half* out = (z == 0) ? g_q : (z == 1) ? g_k : g_v;

    const int arow = tid >> 1, acb = (tid & 1) * 4;
    const int brow = tid >> 2, bcb = (tid & 3) * 2;
    const __half* asrc = g_xh + (size_t)(m0 + arow) * DIM + acb * 8;
    const __half* bsrc = Wh + (size_t)(h * 64 + brow) * DIM + bcb * 8;
    const uint32_t adst = sb + arow * 128;
    const uint32_t bdst = sb + 49152 + brow * 128;

    auto fill = [&](int kt) {
        const int buf = kt % 3;
        #pragma unroll
        for (int c = 0; c < 4; c++) {
            int cc = acb + c;
            CP16(adst + buf * 16384 + ((cc ^ (arow & 7)) << 4), asrc + kt * 64 + c * 8);
        }
        #pragma unroll
        for (int c = 0; c < 2; c++) {
            int cc = bcb + c;
            CP16(bdst + buf * 8192 + ((cc ^ (brow & 7)) << 4), bsrc + kt * 64 + c * 8);
        }
    };
    fill(0); CP_COMMIT();
    fill(1); CP_COMMIT();

    const GemmFrag fr(lane, wid);
    float acc[2][4][4] = {};

    for (int kt = 0; kt < 8; kt++) {
        CP_WAIT1();
        __syncthreads();
        const uint32_t abuf = sb + (kt % 3) * 16384;
        const uint32_t bbuf = sb + 49152 + (kt % 3) * 8192;
        GEMM_KSTEP(abuf, bbuf, acc);
        if (kt < 6) fill(kt + 2);
        CP_COMMIT();
    }

    const int b = m0 >> 10, ns0 = m0 & 1023;
    #pragma unroll
    for (int im = 0; im < 2; im++) {
        int mrow = fr.wm * 32 + im * 16 + fr.g;
        __half* base = out + ((size_t)(b * HEADS + h) * SEQ + ns0 + mrow) * DHEAD;
        #pragma unroll
        for (int nt = 0; nt < 4; nt++) {
            int d = fr.wn * 32 + nt * 8 + 2 * fr.tg;
            *(uint32_t*)(base + d)             = h2u(acc[im][nt][0], acc[im][nt][1]);
            *(uint32_t*)(base + 8 * DHEAD + d) = h2u(acc[im][nt][2], acc[im][nt][3]);
        }
    }
}

// ===========================================================================
// Attention: CTA per (qt, h, b): 128 q-rows, 256 thr (8 warps x 16q).
// 2 kv-tiles per cp.async group (8 waits/syncs instead of 16), 3 buffer
// pairs. f16x2 softmax, P packed directly as PV A-frags, row sums via
// ones-MMA, V^T via ldmatrix.trans, first V frag prefetched under softmax.
// smem: Q 16KB @0; K 3x16KB @16384; V 3x16KB @65536. 112KB, 2 CTAs/SM.
// ===========================================================================
__global__ __launch_bounds__(256, 2) void attn_tc()
{
    extern __shared__ char dsm[];
    const uint32_t sb = smem_u32(dsm);
    const int tid = threadIdx.x, lane = tid & 31, wid = tid >> 5;
    const int qt = blockIdx.x, h = blockIdx.y, b = blockIdx.z;
    const __half* Qg = g_q + ((size_t)(b * HEADS + h) * SEQ + qt * 128) * DHEAD;
    const __half* Kg = g_k + ((size_t)(b * HEADS + h) * SEQ) * DHEAD;
    const __half* Vg = g_v + ((size_t)(b * HEADS + h) * SEQ) * DHEAD;

    // Q fill: 128 rows, 2 thr/row, 4 chunks each
    {
        const int row = tid >> 1, cq = (tid & 1) * 4;
        #pragma unroll
        for (int c = 0; c < 4; c++) {
            int cc = cq + c;
            CP16(sb + row * 128 + ((cc ^ (row & 7)) << 4), Qg + row * 64 + cc * 8);
        }
    }
    // KV fill: group g = kv-tiles {2g, 2g+1} into buffer pair g%3.
    // 64 rows/tile, 4 thr/row, 2 chunks each per matrix per tile.
    const int kvrow = tid >> 2, kvcb = (tid & 3) * 2;
    auto fillKV2 = [&](int gr) {
        const int pair = gr % 3;
        #pragma unroll
        for (int sub = 0; sub < 2; sub++) {
            const int t = 2 * gr + sub;
            #pragma unroll
            for (int c = 0; c < 2; c++) {
                int cc = kvcb + c;
                uint32_t sw = sub * 8192 + kvrow * 128 + ((cc ^ (kvrow & 7)) << 4);
                CP16(sb + 16384 + pair * 16384 + sw,
                     Kg + (size_t)(t * 64 + kvrow) * 64 + cc * 8);
                CP16(sb + 65536 + pair * 16384 + sw,
                     Vg + (size_t)(t * 64 + kvrow) * 64 + cc * 8);
            }
        }
    };
    fillKV2(0); CP_COMMIT();     // group0: Q + kv-tiles 0,1
    fillKV2(1); CP_COMMIT();     // group1: kv-tiles 2,3
    CP_WAIT1();                  // group0 done
    __syncthreads();

    const int g = lane >> 2, tg = lane & 3;
    uint32_t qf[4][4];
    {
        int r = wid * 16 + (lane & 15);
        int cs = lane >> 4;
        #pragma unroll
        for (int ik = 0; ik < 4; ik++) {
            uint32_t ad = sb + r * 128 + (uint32_t)(((2 * ik + cs) ^ (r & 7)) << 4);
            LDSM_X4(qf[ik][0], qf[ik][1], qf[ik][2], qf[ik][3], ad);
        }
    }

    const int br0 = ((lane >> 4) << 3) + (lane & 7);       // K: rows = j
    const int bcs = (lane >> 3) & 1;
    const int vr0 = ((lane >> 3) & 1) * 8 + (lane & 7);    // V trans: rows = j
    const int vcs = lane >> 4;

    auto ldK = [&](uint32_t kb, int ik, int nt2, uint32_t f[4]) {
        int r = nt2 * 16 + br0;
        uint32_t bd = kb + r * 128 + (uint32_t)(((2 * ik + bcs) ^ (r & 7)) << 4);
        LDSM_X4(f[0], f[1], f[2], f[3], bd);
    };
    auto ldV = [&](uint32_t vb, int jk, int dt2, uint32_t f[4]) {
        int r = jk * 16 + vr0;
        uint32_t bd = vb + r * 128 + (uint32_t)(((2 * dt2 + vcs) ^ (r & 7)) << 4);
        LDSM_X4_T(f[0], f[1], f[2], f[3], bd);
    };

    float oc[8][4] = {};
    float rs[4] = {};                    // row-sum MMA accumulator
    const float scl2e = SCALE * LOG2E;
    const float lo = 1e-6f * LOG2E, hi = LOG2E;

    for (int gr = 0; gr < 8; gr++) {
        if (gr) { CP_WAIT1(); __syncthreads(); }
        const int pair = gr % 3;

        #pragma unroll
        for (int sub = 0; sub < 2; sub++) {
            const uint32_t kb = sb + 16384 + pair * 16384 + sub * 8192;
            const uint32_t vb = sb + 65536 + pair * 16384 + sub * 8192;

            // ---- S = Q K^T, pipelined over flattened (ik, nt2) ----
            float sc[8][4] = {};
            uint32_t kf[2][4];
            ldK(kb, 0, 0, kf[0]);
            #pragma unroll
            for (int s = 0; s < 16; s++) {
                const int ik = s >> 2, nt2 = s & 3, cur = s & 1;
                if (s < 15) ldK(kb, (s + 1) >> 2, (s + 1) & 3, kf[cur ^ 1]);
                mma16816(sc[2 * nt2],     qf[ik], kf[cur][0], kf[cur][1]);
                mma16816(sc[2 * nt2 + 1], qf[ik], kf[cur][2], kf[cur][3]);
            }

            // prefetch first V frag so its latency hides under softmax ALU
            uint32_t vf[2][4];
            ldV(vb, 0, 0, vf[0]);

            // ---- P = 2^(clip(S*scale*log2e)) packed f16x2 ----
            uint32_t p[8][2];
            #pragma unroll
            for (int in = 0; in < 8; in++) {
                float x0 = fminf(fmaxf(sc[in][0] * scl2e, lo), hi);
                float x1 = fminf(fmaxf(sc[in][1] * scl2e, lo), hi);
                float x2 = fminf(fmaxf(sc[in][2] * scl2e, lo), hi);
                float x3 = fminf(fmaxf(sc[in][3] * scl2e, lo), hi);
                p[in][0] = ex2h2(h2u(x0, x1));
                p[in][1] = ex2h2(h2u(x2, x3));
            }

            // ---- O += P V; row sums via ones-MMA ----
            uint32_t a[4];
            #pragma unroll
            for (int s = 0; s < 16; s++) {
                const int jk = s >> 2, dt2 = s & 3, cur = s & 1;
                if (dt2 == 0) {
                    a[0] = p[2 * jk][0];
                    a[1] = p[2 * jk][1];
                    a[2] = p[2 * jk + 1][0];
                    a[3] = p[2 * jk + 1][1];
                    mma16816(rs, a, ONESX2, ONESX2);
                }
                if (s < 15) ldV(vb, (s + 1) >> 2, (s + 1) & 3, vf[cur ^ 1]);
                mma16816(oc[2 * dt2],     a, vf[cur][0], vf[cur][1]);
                mma16816(oc[2 * dt2 + 1], a, vf[cur][2], vf[cur][3]);
            }
        }
        if (gr < 6) fillKV2(gr + 2);
        CP_COMMIT();
    }

    const float inv0 = 1.0f / rs[0], inv1 = 1.0f / rs[2];

    __half* ob = g_o + ((size_t)(b * HEADS + h) * SEQ + qt * 128 + wid * 16 + g) * DHEAD;
    #pragma unroll
    for (int dt = 0; dt < 8; dt++) {
        int d = dt * 8 + 2 * tg;
        *(uint32_t*)(ob + d)             = h2u(oc[dt][0] * inv0, oc[dt][1] * inv0);
        *(uint32_t*)(ob + 8 * DHEAD + d) = h2u(oc[dt][2] * inv1, oc[dt][3] * inv1);
    }
}

// ---------------------------------------------------------------------------
// Out-proj: out = concat(g_o) @ Wo^T + bo (fp32). CTA 128m x 64n, grid (8,64).
// ---------------------------------------------------------------------------
__global__ __launch_bounds__(256, 3) void proj_tc(
    const float* __restrict__ bo, float* __restrict__ outp)
{
    extern __shared__ char dsm[];
    const uint32_t sb = smem_u32(dsm);
    const int tid = threadIdx.x, lane = tid & 31, wid = tid >> 5;
    const int nblk = blockIdx.x, m0 = blockIdx.y * 128;
    const int b = m0 >> 10, ns0 = m0 & 1023;

    const int arow = tid >> 1, acb = (tid & 1) * 4;
    const int brow = tid >> 2, bcb = (tid & 3) * 2;
    const __half* bsrc = g_woh + (size_t)(nblk * 64 + brow) * DIM + bcb * 8;
    const uint32_t adst = sb + arow * 128;
    const uint32_t bdst = sb + 49152 + brow * 128;

    auto fill = [&](int kt) {
        const int buf = kt % 3;
        const __half* asrc = g_o + ((size_t)(b * HEADS + kt) * SEQ + ns0 + arow) * DHEAD + acb * 8;
        #pragma unroll
        for (int c = 0; c < 4; c++) {
            int cc = acb + c;
            CP16(adst + buf * 16384 + ((cc ^ (arow & 7)) << 4), asrc + c * 8);
        }
        #pragma unroll
        for (int c = 0; c < 2; c++) {
            int cc = bcb + c;
            CP16(bdst + buf * 8192 + ((cc ^ (brow & 7)) << 4), bsrc + kt * 64 + c * 8);
        }
    };
    fill(0); CP_COMMIT();
    fill(1); CP_COMMIT();

    const GemmFrag fr(lane, wid);
    float acc[2][4][4] = {};

    for (int kt = 0; kt < 8; kt++) {
        CP_WAIT1();
        __syncthreads();
        const uint32_t abuf = sb + (kt % 3) * 16384;
        const uint32_t bbuf = sb + 49152 + (kt % 3) * 8192;
        GEMM_KSTEP(abuf, bbuf, acc);
        if (kt < 6) fill(kt + 2);
        CP_COMMIT();
    }

    #pragma unroll
    for (int im = 0; im < 2; im++) {
        int mrow = m0 + fr.wm * 32 + im * 16 + fr.g;
        #pragma unroll
        for (int nt = 0; nt < 4; nt++) {
            int n = nblk * 64 + fr.wn * 32 + nt * 8 + 2 * fr.tg;
            float2 bias = *(const float2*)(bo + n);
            float* op = outp + (size_t)mrow * DIM + n;
            *(float2*)op = make_float2(acc[im][nt][0] + bias.x, acc[im][nt][1] + bias.y);
            *(float2*)(op + 8 * DIM) = make_float2(acc[im][nt][2] + bias.x,
                                                   acc[im][nt][3] + bias.y);
        }
    }
}

// ---------------------------------------------------------------------------
extern "C" void kernel_launch(void* const* d_in, const int* in_sizes, int n_in,
                              void* d_out, int out_size)
{
    (void)in_sizes; (void)n_in; (void)out_size;
    const float* x  = (const float*)d_in[0];
    const float* wq = (const float*)d_in[1];
    const float* wk = (const float*)d_in[2];
    const float* wv = (const float*)d_in[3];
    const float* wo = (const float*)d_in[4];
    const float* bo = (const float*)d_in[5];
    float* out = (float*)d_out;

    cudaFuncSetAttribute(qkv_tc,  cudaFuncAttributeMaxDynamicSharedMemorySize, 73728);
    cudaFuncSetAttribute(attn_tc, cudaFuncAttributeMaxDynamicSharedMemorySize, 114688);
    cudaFuncSetAttribute(proj_tc, cudaFuncAttributeMaxDynamicSharedMemorySize, 73728);

    conv_k<<<5120, 256>>>(x, wq, wk, wv, wo);
    qkv_tc<<<dim3(HEADS, 64, 3), 256, 73728>>>();
    attn_tc<<<dim3(SEQ / 128, HEADS, BATCH), 256, 114688>>>();
    proj_tc<<<dim3(8, 64), 256, 73728>>>(bo, out);
}